// round 7
// baseline (speedup 1.0000x reference)
#include <cuda_runtime.h>
#include <cuda_bf16.h>
#include <math.h>
#include <stdint.h>

// ---------------- global scratch ----------------
__device__ float    g_outs[76800000];          // layer-1 out_s: 600000 x 128
__device__ uint32_t g_B1h[256 * 128], g_B1l[256 * 128];   // layer-1 B, packed bf16x2 [col][k/2]
__device__ uint32_t g_B2h[128 * 128], g_B2l[128 * 128];   // layer-2 B

// ---------------- helpers ----------------
static __device__ __forceinline__ void split2(float x, float y, uint32_t& ph, uint32_t& pl) {
    __nv_bfloat16 hx = __float2bfloat16(x);
    __nv_bfloat16 hy = __float2bfloat16(y);
    float rx = x - __bfloat162float(hx);
    float ry = y - __bfloat162float(hy);
    __nv_bfloat162 H; H.x = hx; H.y = hy;
    __nv_bfloat162 L; L.x = __float2bfloat16(rx); L.y = __float2bfloat16(ry);
    ph = *reinterpret_cast<uint32_t*>(&H);
    pl = *reinterpret_cast<uint32_t*>(&L);
}

static __device__ __forceinline__ void mma16(float c[4], const uint32_t a[4],
                                             uint32_t b0, uint32_t b1) {
    asm volatile(
        "mma.sync.aligned.m16n8k16.row.col.f32.bf16.bf16.f32 "
        "{%0,%1,%2,%3}, {%4,%5,%6,%7}, {%8,%9}, {%0,%1,%2,%3};"
        : "+f"(c[0]), "+f"(c[1]), "+f"(c[2]), "+f"(c[3])
        : "r"(a[0]), "r"(a[1]), "r"(a[2]), "r"(a[3]), "r"(b0), "r"(b1));
}

static __device__ __forceinline__ void ldsm4(uint32_t& r0, uint32_t& r1,
                                             uint32_t& r2, uint32_t& r3, uint32_t saddr) {
    asm volatile("ldmatrix.sync.aligned.m8n8.x4.shared.b16 {%0,%1,%2,%3}, [%4];"
                 : "=r"(r0), "=r"(r1), "=r"(r2), "=r"(r3) : "r"(saddr));
}

static __device__ __forceinline__ void cpa16(uint32_t* dst, const uint32_t* src) {
    uint32_t s = (uint32_t)__cvta_generic_to_shared(dst);
    asm volatile("cp.async.cg.shared.global [%0], [%1], 16;\n" :: "r"(s), "l"(src));
}
static __device__ __forceinline__ void cpa_commit() {
    asm volatile("cp.async.commit_group;\n" ::: "memory");
}

static __device__ __forceinline__ float sigmoidf_(float v) {
    return 1.0f / (1.0f + expf(-v));
}

// exact-ish recompute of t for spike decisions near the threshold
static __device__ __noinline__ float recompute_t(const uint32_t* AHrow, const uint32_t* ALrow,
                                                 const float* __restrict__ wt,
                                                 const float* __restrict__ wr) {
    float s = 0.0f;
    for (int k2 = 0; k2 < 64; k2++) {
        __nv_bfloat162 uh = *reinterpret_cast<const __nv_bfloat162*>(&AHrow[k2]);
        __nv_bfloat162 ul = *reinterpret_cast<const __nv_bfloat162*>(&ALrow[k2]);
        float a0 = __bfloat162float(uh.x) + __bfloat162float(ul.x);
        float a1 = __bfloat162float(uh.y) + __bfloat162float(ul.y);
        s += a0 * wt[2 * k2] + a1 * wt[2 * k2 + 1];
    }
    for (int k2 = 64; k2 < 128; k2++) {
        __nv_bfloat162 uh = *reinterpret_cast<const __nv_bfloat162*>(&AHrow[k2]);
        __nv_bfloat162 ul = *reinterpret_cast<const __nv_bfloat162*>(&ALrow[k2]);
        float a0 = __bfloat162float(uh.x) + __bfloat162float(ul.x);
        float a1 = __bfloat162float(uh.y) + __bfloat162float(ul.y);
        s += a0 * wr[2 * k2 - 128] + a1 * wr[2 * k2 - 127];
    }
    return s;
}

// ---------------- weight pre-split ----------------
__global__ void presplit(const float* __restrict__ Wl1, const float* __restrict__ Wr1,
                         const float* __restrict__ Wlt1, const float* __restrict__ Wrt1,
                         const float* __restrict__ Wl2, const float* __restrict__ Wr2,
                         const float* __restrict__ Wlt2, const float* __restrict__ Wrt2) {
    int c = blockIdx.x;          // 0..383
    int t = threadIdx.x;         // 0..127 -> k pair (2t, 2t+1)
    bool is1 = c < 256;
    int cc = is1 ? c : c - 256;
    int j = cc >> 1, tt = cc & 1;
    int k = 2 * t;
    const float* base;
    if (is1) base = (k < 128) ? (tt ? Wlt1 : Wl1) : (tt ? Wrt1 : Wr1);
    else     base = (k < 128) ? (tt ? Wlt2 : Wl2) : (tt ? Wrt2 : Wr2);
    int kk = k & 127;
    float x = base[j * 128 + kk], y = base[j * 128 + kk + 1];
    uint32_t ph, pl;
    split2(x, y, ph, pl);
    if (is1) { g_B1h[cc * 128 + t] = ph; g_B1l[cc * 128 + t] = pl; }
    else     { g_B2h[cc * 128 + t] = ph; g_B2l[cc * 128 + t] = pl; }
}

// ---------------- fused GEMM + epilogue ----------------
#define AP 132   // uint32 per A row (128 data + 4 pad) -> 528B row stride
#define BP 20    // uint32 per B col per 32-k chunk (16 data + 4 pad) -> 80B col stride

template <bool L1>
__global__ void __launch_bounds__(512, 1)
signn_gemm(const float* __restrict__ h0, const float* __restrict__ h1,
           const float* __restrict__ h2,
           const float* __restrict__ Wt_self, const float* __restrict__ Wt_neigh,
           float* __restrict__ outp, int N)
{
    constexpr int NCOL = L1 ? 256 : 128;
    constexpr int NTI  = NCOL / 32;      // 8-col n-tiles per warp
    constexpr int OC   = L1 ? 128 : 64;  // output cols

    extern __shared__ uint32_t sm[];
    uint32_t* AH = sm;
    uint32_t* AL = sm + 128 * AP;
    uint32_t* Bb = sm + 2 * 128 * AP;    // 4 segments: [buf][h/l], each NCOL*BP

    const int tid = threadIdx.x;
    const int w = tid >> 5, l = tid & 31;
    const int g = l >> 2, tg = l & 3;
    const int warpM = w >> 2, warpN = w & 3;
    const long rows = L1 ? 6L * N : (long)N;
    const long blockRow = (long)blockIdx.x * 128;
    const uint32_t* Bh = L1 ? g_B1h : g_B2h;
    const uint32_t* Bl = L1 ? g_B1l : g_B2l;
    float* op = L1 ? g_outs : outp;

    // ldmatrix lane geometry
    const int rowA = l & 15;                        // A tile row
    const int kofA = (l >= 16) ? 8 : 0;             // A k offset (bf16 units)
    const int nofB = (l & 7) + ((l >= 16) ? 8 : 0); // B n within 16-wide pair
    const int kofB = (l & 8) ? 8 : 0;               // B k offset (bf16 units)

    // ---- prefetch B chunk 0 via cp.async (overlaps A staging) ----
    {
#pragma unroll
        for (int arr = 0; arr < 2; arr++) {
            const uint32_t* src = arr ? Bl : Bh;
            uint32_t* dst = Bb + arr * NCOL * BP;
#pragma unroll
            for (int it = 0; it < NCOL * 4 / 512; it++) {
                int o = it * 512 + tid;
                int col = o >> 2, q = o & 3;
                cpa16(dst + col * BP + 4 * q, src + col * 128 + 4 * q);
            }
        }
        cpa_commit();
    }

    // ---- stage A: gather rows, split to bf16 hi/lo, pack pairs ----
#pragma unroll
    for (int rr = 0; rr < 8; rr++) {
        int row = w * 8 + rr;
        long gr = blockRow + row;
        long grc = gr < rows ? gr : rows - 1;
        float4 xv, nv;
        if (L1) {
            if (grc < N) {
                xv = ((const float4*)h0)[grc * 32 + l];
                const float4* p = (const float4*)h1 + grc * 5 * 32 + l;
                float4 a0 = p[0], a1 = p[32], a2 = p[64], a3 = p[96], a4 = p[128];
                nv.x = (a0.x + a1.x + a2.x + a3.x + a4.x) * 0.2f;
                nv.y = (a0.y + a1.y + a2.y + a3.y + a4.y) * 0.2f;
                nv.z = (a0.z + a1.z + a2.z + a3.z + a4.z) * 0.2f;
                nv.w = (a0.w + a1.w + a2.w + a3.w + a4.w) * 0.2f;
            } else {
                long q = grc - N;
                xv = ((const float4*)h1)[q * 32 + l];
                const float4* p = (const float4*)h2 + q * 2 * 32 + l;
                float4 a0 = p[0], a1 = p[32];
                nv.x = (a0.x + a1.x) * 0.5f;
                nv.y = (a0.y + a1.y) * 0.5f;
                nv.z = (a0.z + a1.z) * 0.5f;
                nv.w = (a0.w + a1.w) * 0.5f;
            }
        } else {
            xv = ((const float4*)g_outs)[grc * 32 + l];
            const float4* p = (const float4*)g_outs + ((long)N + grc * 5) * 32 + l;
            float4 a0 = p[0], a1 = p[32], a2 = p[64], a3 = p[96], a4 = p[128];
            nv.x = (a0.x + a1.x + a2.x + a3.x + a4.x) * 0.2f;
            nv.y = (a0.y + a1.y + a2.y + a3.y + a4.y) * 0.2f;
            nv.z = (a0.z + a1.z + a2.z + a3.z + a4.z) * 0.2f;
            nv.w = (a0.w + a1.w + a2.w + a3.w + a4.w) * 0.2f;
        }
        uint32_t h0p, l0p, h1p, l1p;
        split2(xv.x, xv.y, h0p, l0p);
        split2(xv.z, xv.w, h1p, l1p);
        *(uint2*)&AH[row * AP + 2 * l] = make_uint2(h0p, h1p);
        *(uint2*)&AL[row * AP + 2 * l] = make_uint2(l0p, l1p);
        split2(nv.x, nv.y, h0p, l0p);
        split2(nv.z, nv.w, h1p, l1p);
        *(uint2*)&AH[row * AP + 64 + 2 * l] = make_uint2(h0p, h1p);
        *(uint2*)&AL[row * AP + 64 + 2 * l] = make_uint2(l0p, l1p);
    }

    float acc[2][NTI][4];
#pragma unroll
    for (int mt = 0; mt < 2; mt++)
#pragma unroll
        for (int nt = 0; nt < NTI; nt++)
#pragma unroll
            for (int e = 0; e < 4; e++) acc[mt][nt][e] = 0.0f;

    // per-thread ldmatrix shared addresses (byte offsets)
    const uint32_t aHbase = (uint32_t)__cvta_generic_to_shared(AH);
    const uint32_t aLbase = (uint32_t)__cvta_generic_to_shared(AL);
    const uint32_t bBase  = (uint32_t)__cvta_generic_to_shared(Bb);

    // ---- main loop: 8 chunks of BK=32, 1-ahead cp.async pipeline, ONE sync/chunk ----
#pragma unroll 1
    for (int kc = 0; kc < 8; kc++) {
        asm volatile("cp.async.wait_group 0;\n" ::: "memory");
        __syncthreads();
        // all warps have finished reading buffer (kc+1)&1 (their kc-1 MMAs precede
        // this barrier), and chunk kc data is visible -> safe to overwrite now.
        if (kc < 7) {
            uint32_t* base = Bb + ((kc + 1) & 1) * 2 * NCOL * BP;
#pragma unroll
            for (int arr = 0; arr < 2; arr++) {
                const uint32_t* src = (arr ? Bl : Bh) + (kc + 1) * 16;
                uint32_t* dst = base + arr * NCOL * BP;
#pragma unroll
                for (int it = 0; it < NCOL * 4 / 512; it++) {
                    int o = it * 512 + tid;
                    int col = o >> 2, q = o & 3;
                    cpa16(dst + col * BP + 4 * q, src + col * 128 + 4 * q);
                }
            }
            cpa_commit();
        }

        const uint32_t bHc = bBase + ((kc & 1) * 2 * NCOL * BP) * 4;
        const uint32_t bLc = bHc + NCOL * BP * 4;
#pragma unroll
        for (int ks = 0; ks < 2; ks++) {
            int kb = kc * 32 + ks * 16;   // global k (bf16 units)
            uint32_t ah[2][4], al[2][4];
#pragma unroll
            for (int mt = 0; mt < 2; mt++) {
                uint32_t ro = (uint32_t)(warpM * 32 + mt * 16 + rowA) * (AP * 4)
                            + (kb + kofA) * 2;
                ldsm4(ah[mt][0], ah[mt][1], ah[mt][2], ah[mt][3], aHbase + ro);
                ldsm4(al[mt][0], al[mt][1], al[mt][2], al[mt][3], aLbase + ro);
            }
#pragma unroll
            for (int ntp = 0; ntp < NTI / 2; ntp++) {
                uint32_t co = (uint32_t)(warpN * (NTI * 8) + ntp * 16 + nofB) * (BP * 4)
                            + (ks * 16 + kofB) * 2;
                uint32_t bh[4], bl[4];
                ldsm4(bh[0], bh[1], bh[2], bh[3], bHc + co);
                ldsm4(bl[0], bl[1], bl[2], bl[3], bLc + co);
                // term-major issue order: same-accumulator RAW distance = 4
#pragma unroll
                for (int tile = 0; tile < 2; tile++)
#pragma unroll
                    for (int mt = 0; mt < 2; mt++)
                        mma16(acc[mt][ntp * 2 + tile], ah[mt], bh[2 * tile], bh[2 * tile + 1]);
#pragma unroll
                for (int tile = 0; tile < 2; tile++)
#pragma unroll
                    for (int mt = 0; mt < 2; mt++)
                        mma16(acc[mt][ntp * 2 + tile], ah[mt], bl[2 * tile], bl[2 * tile + 1]);
#pragma unroll
                for (int tile = 0; tile < 2; tile++)
#pragma unroll
                    for (int mt = 0; mt < 2; mt++)
                        mma16(acc[mt][ntp * 2 + tile], al[mt], bh[2 * tile], bh[2 * tile + 1]);
            }
        }
    }

    // ---- epilogue: out = sigmoid(x) * spike(t), guarded near threshold ----
#pragma unroll
    for (int mt = 0; mt < 2; mt++) {
#pragma unroll
        for (int nt = 0; nt < NTI; nt++) {
            int j = warpN * (NTI * 4) + nt * 4 + tg;
#pragma unroll
            for (int half = 0; half < 2; half++) {
                int rloc = warpM * 32 + mt * 16 + g + half * 8;
                long gr = blockRow + rloc;
                if (gr < rows) {
                    float x = acc[mt][nt][half * 2 + 0];
                    float t = acc[mt][nt][half * 2 + 1];
                    if (fabsf(t - 1.0f) < 5e-4f)
                        t = recompute_t(&AH[rloc * AP], &AL[rloc * AP],
                                        Wt_self + j * 128, Wt_neigh + j * 128);
                    op[gr * OC + j] = (t >= 1.0f) ? sigmoidf_(x) : 0.0f;
                }
            }
        }
    }
}

extern "C" void kernel_launch(void* const* d_in, const int* in_sizes, int n_in,
                              void* d_out, int out_size)
{
    const float* h0   = (const float*)d_in[0];
    const float* h1   = (const float*)d_in[1];
    const float* h2   = (const float*)d_in[2];
    const float* Wl1  = (const float*)d_in[3];
    const float* Wr1  = (const float*)d_in[4];
    const float* Wlt1 = (const float*)d_in[5];
    const float* Wrt1 = (const float*)d_in[6];
    const float* Wl2  = (const float*)d_in[7];
    const float* Wr2  = (const float*)d_in[8];
    const float* Wlt2 = (const float*)d_in[9];
    const float* Wrt2 = (const float*)d_in[10];

    int N = in_sizes[0] / 128;

    int smem1 = (2 * 128 * AP + 4 * 256 * BP) * 4;   // 217,088 B
    int smem2 = (2 * 128 * AP + 4 * 128 * BP) * 4;   // 176,128 B
    cudaFuncSetAttribute(signn_gemm<true>,  cudaFuncAttributeMaxDynamicSharedMemorySize, smem1);
    cudaFuncSetAttribute(signn_gemm<false>, cudaFuncAttributeMaxDynamicSharedMemorySize, smem2);

    long rows = 6L * N;
    int grid1 = (int)((rows + 127) / 128);
    int grid2 = (N + 127) / 128;

    presplit<<<384, 128>>>(Wl1, Wr1, Wlt1, Wrt1, Wl2, Wr2, Wlt2, Wrt2);
    signn_gemm<true><<<grid1, 512, smem1>>>(h0, h1, h2, Wlt1, Wrt1, nullptr, N);
    signn_gemm<false><<<grid2, 512, smem2>>>(nullptr, nullptr, nullptr, Wlt2, Wrt2,
                                             (float*)d_out, N);
}

// round 8
// speedup vs baseline: 1.0795x; 1.0795x over previous
#include <cuda_runtime.h>
#include <cuda_bf16.h>
#include <math.h>
#include <stdint.h>

// ---------------- global scratch ----------------
__device__ float    g_outs[76800000];     // layer-1 out_s: 600000 x 128
// B weights, pre-split bf16 hi/lo, chunk-major padded: [chunk(8)][col][20 u32]
// (16 u32 = 32 k-values packed bf16x2, + 4 u32 pad so smem col stride = 80B)
__device__ uint32_t g_B1h[8 * 256 * 20], g_B1l[8 * 256 * 20];
__device__ uint32_t g_B2h[8 * 128 * 20], g_B2l[8 * 128 * 20];

// ---------------- helpers ----------------
static __device__ __forceinline__ void split2(float x, float y, uint32_t& ph, uint32_t& pl) {
    __nv_bfloat16 hx = __float2bfloat16(x);
    __nv_bfloat16 hy = __float2bfloat16(y);
    float rx = x - __bfloat162float(hx);
    float ry = y - __bfloat162float(hy);
    __nv_bfloat162 H; H.x = hx; H.y = hy;
    __nv_bfloat162 L; L.x = __float2bfloat16(rx); L.y = __float2bfloat16(ry);
    ph = *reinterpret_cast<uint32_t*>(&H);
    pl = *reinterpret_cast<uint32_t*>(&L);
}

static __device__ __forceinline__ void mma16(float c[4], const uint32_t a[4],
                                             uint32_t b0, uint32_t b1) {
    asm volatile(
        "mma.sync.aligned.m16n8k16.row.col.f32.bf16.bf16.f32 "
        "{%0,%1,%2,%3}, {%4,%5,%6,%7}, {%8,%9}, {%0,%1,%2,%3};"
        : "+f"(c[0]), "+f"(c[1]), "+f"(c[2]), "+f"(c[3])
        : "r"(a[0]), "r"(a[1]), "r"(a[2]), "r"(a[3]), "r"(b0), "r"(b1));
}

static __device__ __forceinline__ void ldsm4(uint32_t& r0, uint32_t& r1,
                                             uint32_t& r2, uint32_t& r3, uint32_t saddr) {
    asm volatile("ldmatrix.sync.aligned.m8n8.x4.shared.b16 {%0,%1,%2,%3}, [%4];"
                 : "=r"(r0), "=r"(r1), "=r"(r2), "=r"(r3) : "r"(saddr));
}

static __device__ __forceinline__ void bulk_g2s(uint32_t dst, const void* src,
                                                uint32_t bytes, uint32_t mbar) {
    asm volatile(
        "cp.async.bulk.shared::cta.global.mbarrier::complete_tx::bytes [%0], [%1], %2, [%3];"
        :: "r"(dst), "l"(src), "r"(bytes), "r"(mbar) : "memory");
}

static __device__ __forceinline__ void mbar_expect(uint32_t mbar, uint32_t bytes) {
    asm volatile("mbarrier.arrive.expect_tx.shared.b64 _, [%0], %1;"
                 :: "r"(mbar), "r"(bytes) : "memory");
}

static __device__ __forceinline__ void mbar_wait(uint32_t mbar, uint32_t parity) {
    asm volatile(
        "{\n\t.reg .pred P1;\n\t"
        "WL_%=:\n\t"
        "mbarrier.try_wait.parity.acquire.cta.shared::cta.b64 P1, [%0], %1, 0x989680;\n\t"
        "@P1 bra.uni WD_%=;\n\t"
        "bra.uni WL_%=;\n\t"
        "WD_%=:\n\t}"
        :: "r"(mbar), "r"(parity) : "memory");
}

static __device__ __forceinline__ float sigmoidf_(float v) {
    return 1.0f / (1.0f + expf(-v));
}

// exact-ish recompute of t for spike decisions near the threshold
static __device__ __noinline__ float recompute_t(const uint32_t* AHrow, const uint32_t* ALrow,
                                                 const float* __restrict__ wt,
                                                 const float* __restrict__ wr) {
    float s = 0.0f;
    for (int k2 = 0; k2 < 64; k2++) {
        __nv_bfloat162 uh = *reinterpret_cast<const __nv_bfloat162*>(&AHrow[k2]);
        __nv_bfloat162 ul = *reinterpret_cast<const __nv_bfloat162*>(&ALrow[k2]);
        float a0 = __bfloat162float(uh.x) + __bfloat162float(ul.x);
        float a1 = __bfloat162float(uh.y) + __bfloat162float(ul.y);
        s += a0 * wt[2 * k2] + a1 * wt[2 * k2 + 1];
    }
    for (int k2 = 64; k2 < 128; k2++) {
        __nv_bfloat162 uh = *reinterpret_cast<const __nv_bfloat162*>(&AHrow[k2]);
        __nv_bfloat162 ul = *reinterpret_cast<const __nv_bfloat162*>(&ALrow[k2]);
        float a0 = __bfloat162float(uh.x) + __bfloat162float(ul.x);
        float a1 = __bfloat162float(uh.y) + __bfloat162float(ul.y);
        s += a0 * wr[2 * k2 - 128] + a1 * wr[2 * k2 - 127];
    }
    return s;
}

// ---------------- weight pre-split (chunk-major padded layout) ----------------
// col c (interleaved): j = c>>1, tt = c&1 (0 -> x-gate Wl/Wr, 1 -> t-gate Wlt/Wrt)
// global k < 128 -> self weights, k >= 128 -> neigh weights.
__global__ void presplit(const float* __restrict__ Wl1, const float* __restrict__ Wr1,
                         const float* __restrict__ Wlt1, const float* __restrict__ Wrt1,
                         const float* __restrict__ Wl2, const float* __restrict__ Wr2,
                         const float* __restrict__ Wlt2, const float* __restrict__ Wrt2) {
    int c = blockIdx.x;          // 0..383
    int t = threadIdx.x;         // 0..127 -> k pair (2t, 2t+1)
    bool is1 = c < 256;
    int cc = is1 ? c : c - 256;
    int ncol = is1 ? 256 : 128;
    int j = cc >> 1, tt = cc & 1;
    int k = 2 * t;
    const float* base;
    if (is1) base = (k < 128) ? (tt ? Wlt1 : Wl1) : (tt ? Wrt1 : Wr1);
    else     base = (k < 128) ? (tt ? Wlt2 : Wl2) : (tt ? Wrt2 : Wr2);
    int kk = k & 127;
    float x = base[j * 128 + kk], y = base[j * 128 + kk + 1];
    uint32_t ph, pl;
    split2(x, y, ph, pl);
    int chunk = t >> 4, p = t & 15;
    long idx = ((long)chunk * ncol + cc) * 20 + p;
    if (is1) { g_B1h[idx] = ph; g_B1l[idx] = pl; }
    else     { g_B2h[idx] = ph; g_B2l[idx] = pl; }
}

// ---------------- fused GEMM + epilogue ----------------
#define AP 132   // uint32 per A row (128 data + 4 pad) -> 528B row stride
#define BP 20    // uint32 per B col per 32-k chunk (16 data + 4 pad) -> 80B col stride

template <bool L1>
__global__ void __launch_bounds__(512, 1)
signn_gemm(const float* __restrict__ h0, const float* __restrict__ h1,
           const float* __restrict__ h2,
           const float* __restrict__ Wt_self, const float* __restrict__ Wt_neigh,
           float* __restrict__ outp, int N)
{
    constexpr int NCOL = L1 ? 256 : 128;
    constexpr int NTI  = NCOL / 32;      // 8-col n-tiles per warp
    constexpr int OC   = L1 ? 128 : 64;  // output cols
    constexpr uint32_t CHUNK_U32 = NCOL * BP;            // one h or l chunk, u32
    constexpr uint32_t CHUNK_B   = CHUNK_U32 * 4;        // bytes
    constexpr uint32_t PAIR_B    = 2 * CHUNK_B;          // hi+lo per buffer fill

    extern __shared__ uint32_t sm[];
    uint32_t* AH = sm;
    uint32_t* AL = sm + 128 * AP;
    uint32_t* Bb = sm + 2 * 128 * AP;    // 2 buffers x (hi chunk + lo chunk)
    uint32_t* mbars = Bb + 2 * 2 * CHUNK_U32;   // 2 mbarriers (8B each)

    const int tid = threadIdx.x;
    const int w = tid >> 5, l = tid & 31;
    const int g = l >> 2, tg = l & 3;
    const int warpM = w >> 2, warpN = w & 3;
    const long rows = L1 ? 6L * N : (long)N;
    const long blockRow = (long)blockIdx.x * 128;
    const uint32_t* Bh = L1 ? g_B1h : g_B2h;
    const uint32_t* Bl = L1 ? g_B1l : g_B2l;
    float* op = L1 ? g_outs : outp;

    const uint32_t mb0 = (uint32_t)__cvta_generic_to_shared(mbars);
    const uint32_t mb1 = mb0 + 8;
    const uint32_t bBase = (uint32_t)__cvta_generic_to_shared(Bb);

    // ldmatrix lane geometry
    const int rowA = l & 15;                        // A tile row
    const int kofA = (l >= 16) ? 8 : 0;             // A k offset (bf16 units)
    const int nofB = (l & 7) + ((l >= 16) ? 8 : 0); // B n within 16-wide pair
    const int kofB = (l & 8) ? 8 : 0;               // B k offset (bf16 units)

    // ---- init mbarriers ----
    if (tid == 0) {
        asm volatile("mbarrier.init.shared.b64 [%0], 1;" :: "r"(mb0) : "memory");
        asm volatile("mbarrier.init.shared.b64 [%0], 1;" :: "r"(mb1) : "memory");
    }
    __syncthreads();

    // ---- kick off bulk prefetch of chunks 0 and 1 (overlaps A staging) ----
    if (tid == 0) {
        mbar_expect(mb0, PAIR_B);
        bulk_g2s(bBase,           Bh + 0 * CHUNK_U32, CHUNK_B, mb0);
        bulk_g2s(bBase + CHUNK_B, Bl + 0 * CHUNK_U32, CHUNK_B, mb0);
        mbar_expect(mb1, PAIR_B);
        bulk_g2s(bBase + PAIR_B,           Bh + 1 * CHUNK_U32, CHUNK_B, mb1);
        bulk_g2s(bBase + PAIR_B + CHUNK_B, Bl + 1 * CHUNK_U32, CHUNK_B, mb1);
    }

    // ---- stage A: gather rows, split to bf16 hi/lo, pack pairs ----
#pragma unroll
    for (int rr = 0; rr < 8; rr++) {
        int row = w * 8 + rr;
        long gr = blockRow + row;
        long grc = gr < rows ? gr : rows - 1;
        float4 xv, nv;
        if (L1) {
            if (grc < N) {
                xv = ((const float4*)h0)[grc * 32 + l];
                const float4* p = (const float4*)h1 + grc * 5 * 32 + l;
                float4 a0 = p[0], a1 = p[32], a2 = p[64], a3 = p[96], a4 = p[128];
                nv.x = (a0.x + a1.x + a2.x + a3.x + a4.x) * 0.2f;
                nv.y = (a0.y + a1.y + a2.y + a3.y + a4.y) * 0.2f;
                nv.z = (a0.z + a1.z + a2.z + a3.z + a4.z) * 0.2f;
                nv.w = (a0.w + a1.w + a2.w + a3.w + a4.w) * 0.2f;
            } else {
                long q = grc - N;
                xv = ((const float4*)h1)[q * 32 + l];
                const float4* p = (const float4*)h2 + q * 2 * 32 + l;
                float4 a0 = p[0], a1 = p[32];
                nv.x = (a0.x + a1.x) * 0.5f;
                nv.y = (a0.y + a1.y) * 0.5f;
                nv.z = (a0.z + a1.z) * 0.5f;
                nv.w = (a0.w + a1.w) * 0.5f;
            }
        } else {
            xv = ((const float4*)g_outs)[grc * 32 + l];
            const float4* p = (const float4*)g_outs + ((long)N + grc * 5) * 32 + l;
            float4 a0 = p[0], a1 = p[32], a2 = p[64], a3 = p[96], a4 = p[128];
            nv.x = (a0.x + a1.x + a2.x + a3.x + a4.x) * 0.2f;
            nv.y = (a0.y + a1.y + a2.y + a3.y + a4.y) * 0.2f;
            nv.z = (a0.z + a1.z + a2.z + a3.z + a4.z) * 0.2f;
            nv.w = (a0.w + a1.w + a2.w + a3.w + a4.w) * 0.2f;
        }
        uint32_t h0p, l0p, h1p, l1p;
        split2(xv.x, xv.y, h0p, l0p);
        split2(xv.z, xv.w, h1p, l1p);
        *(uint2*)&AH[row * AP + 2 * l] = make_uint2(h0p, h1p);
        *(uint2*)&AL[row * AP + 2 * l] = make_uint2(l0p, l1p);
        split2(nv.x, nv.y, h0p, l0p);
        split2(nv.z, nv.w, h1p, l1p);
        *(uint2*)&AH[row * AP + 64 + 2 * l] = make_uint2(h0p, h1p);
        *(uint2*)&AL[row * AP + 64 + 2 * l] = make_uint2(l0p, l1p);
    }
    __syncthreads();   // A visible to all warps before ldsm

    float acc[2][NTI][4];
#pragma unroll
    for (int mt = 0; mt < 2; mt++)
#pragma unroll
        for (int nt = 0; nt < NTI; nt++)
#pragma unroll
            for (int e = 0; e < 4; e++) acc[mt][nt][e] = 0.0f;

    const uint32_t aHbase = (uint32_t)__cvta_generic_to_shared(AH);
    const uint32_t aLbase = (uint32_t)__cvta_generic_to_shared(AL);

    // ---- main loop: 8 chunks of BK=32, double-buffered via bulk DMA ----
#pragma unroll 1
    for (int kc = 0; kc < 8; kc++) {
        const int b = kc & 1;
        const uint32_t mbb = b ? mb1 : mb0;
        mbar_wait(mbb, (kc >> 1) & 1);     // chunk kc data ready

        const uint32_t bHc = bBase + b * PAIR_B;
        const uint32_t bLc = bHc + CHUNK_B;
#pragma unroll
        for (int ks = 0; ks < 2; ks++) {
            int kb = kc * 32 + ks * 16;   // global k (bf16 units)
            uint32_t ah[2][4], al[2][4];
#pragma unroll
            for (int mt = 0; mt < 2; mt++) {
                uint32_t ro = (uint32_t)(warpM * 32 + mt * 16 + rowA) * (AP * 4)
                            + (kb + kofA) * 2;
                ldsm4(ah[mt][0], ah[mt][1], ah[mt][2], ah[mt][3], aHbase + ro);
                ldsm4(al[mt][0], al[mt][1], al[mt][2], al[mt][3], aLbase + ro);
            }
#pragma unroll
            for (int ntp = 0; ntp < NTI / 2; ntp++) {
                uint32_t co = (uint32_t)(warpN * (NTI * 8) + ntp * 16 + nofB) * (BP * 4)
                            + (ks * 16 + kofB) * 2;
                uint32_t bh[4], bl[4];
                ldsm4(bh[0], bh[1], bh[2], bh[3], bHc + co);
                ldsm4(bl[0], bl[1], bl[2], bl[3], bLc + co);
#pragma unroll
                for (int tile = 0; tile < 2; tile++) {
                    int nt = ntp * 2 + tile;
#pragma unroll
                    for (int mt = 0; mt < 2; mt++) {
                        mma16(acc[mt][nt], ah[mt], bh[2 * tile], bh[2 * tile + 1]);
                        mma16(acc[mt][nt], ah[mt], bl[2 * tile], bl[2 * tile + 1]);
                        mma16(acc[mt][nt], al[mt], bh[2 * tile], bh[2 * tile + 1]);
                    }
                }
            }
        }

        if (kc + 2 < 8) {
            __syncthreads();   // all warps done reading buffer b for chunk kc
            if (tid == 0) {
                mbar_expect(mbb, PAIR_B);
                bulk_g2s(bBase + b * PAIR_B,           Bh + (kc + 2) * CHUNK_U32, CHUNK_B, mbb);
                bulk_g2s(bBase + b * PAIR_B + CHUNK_B, Bl + (kc + 2) * CHUNK_U32, CHUNK_B, mbb);
            }
        }
    }

    // ---- epilogue: out = sigmoid(x) * spike(t), guarded near threshold ----
#pragma unroll
    for (int mt = 0; mt < 2; mt++) {
#pragma unroll
        for (int nt = 0; nt < NTI; nt++) {
            int j = warpN * (NTI * 4) + nt * 4 + tg;
#pragma unroll
            for (int half = 0; half < 2; half++) {
                int rloc = warpM * 32 + mt * 16 + g + half * 8;
                long gr = blockRow + rloc;
                if (gr < rows) {
                    float x = acc[mt][nt][half * 2 + 0];
                    float t = acc[mt][nt][half * 2 + 1];
                    if (fabsf(t - 1.0f) < 5e-4f)
                        t = recompute_t(&AH[rloc * AP], &AL[rloc * AP],
                                        Wt_self + j * 128, Wt_neigh + j * 128);
                    op[gr * OC + j] = (t >= 1.0f) ? sigmoidf_(x) : 0.0f;
                }
            }
        }
    }
}

extern "C" void kernel_launch(void* const* d_in, const int* in_sizes, int n_in,
                              void* d_out, int out_size)
{
    const float* h0   = (const float*)d_in[0];
    const float* h1   = (const float*)d_in[1];
    const float* h2   = (const float*)d_in[2];
    const float* Wl1  = (const float*)d_in[3];
    const float* Wr1  = (const float*)d_in[4];
    const float* Wlt1 = (const float*)d_in[5];
    const float* Wrt1 = (const float*)d_in[6];
    const float* Wl2  = (const float*)d_in[7];
    const float* Wr2  = (const float*)d_in[8];
    const float* Wlt2 = (const float*)d_in[9];
    const float* Wrt2 = (const float*)d_in[10];

    int N = in_sizes[0] / 128;

    int smem1 = (2 * 128 * AP + 4 * 256 * BP) * 4 + 64;   // A + 2x(h,l) B bufs + mbars
    int smem2 = (2 * 128 * AP + 4 * 128 * BP) * 4 + 64;
    cudaFuncSetAttribute(signn_gemm<true>,  cudaFuncAttributeMaxDynamicSharedMemorySize, smem1);
    cudaFuncSetAttribute(signn_gemm<false>, cudaFuncAttributeMaxDynamicSharedMemorySize, smem2);

    long rows = 6L * N;
    int grid1 = (int)((rows + 127) / 128);
    int grid2 = (N + 127) / 128;

    presplit<<<384, 128>>>(Wl1, Wr1, Wlt1, Wrt1, Wl2, Wr2, Wlt2, Wrt2);
    signn_gemm<true><<<grid1, 512, smem1>>>(h0, h1, h2, Wlt1, Wrt1, nullptr, N);
    signn_gemm<false><<<grid2, 512, smem2>>>(nullptr, nullptr, nullptr, Wlt2, Wrt2,
                                             (float*)d_out, N);
}

// round 9
// speedup vs baseline: 1.2565x; 1.1640x over previous
#include <cuda_runtime.h>
#include <cuda_fp16.h>
#include <math.h>
#include <stdint.h>

// ---------------- global scratch ----------------
__device__ float    g_outs[76800000];     // layer-1 out_s: 600000 x 128 (fp32)
// B weights, pre-split fp16 hi/lo, DE-INTERLEAVED (x cols then t cols),
// chunk-major padded: [chunk(8)][col][20 u32] (16 u32 = 32 k packed half2 + 4 pad)
__device__ uint32_t g_B1h[8 * 256 * 20], g_B1l[8 * 256 * 20];
__device__ uint32_t g_B2h[8 * 128 * 20], g_B2l[8 * 128 * 20];

// ---------------- helpers ----------------
static __device__ __forceinline__ void split2h(float x, float y, uint32_t& ph, uint32_t& pl) {
    __half hx = __float2half(x);
    __half hy = __float2half(y);
    float rx = x - __half2float(hx);
    float ry = y - __half2float(hy);
    __half2 H = __halves2half2(hx, hy);
    __half2 L = __halves2half2(__float2half(rx), __float2half(ry));
    ph = *reinterpret_cast<uint32_t*>(&H);
    pl = *reinterpret_cast<uint32_t*>(&L);
}

static __device__ __forceinline__ void mma16(float c[4], const uint32_t a[4],
                                             uint32_t b0, uint32_t b1) {
    asm volatile(
        "mma.sync.aligned.m16n8k16.row.col.f32.f16.f16.f32 "
        "{%0,%1,%2,%3}, {%4,%5,%6,%7}, {%8,%9}, {%0,%1,%2,%3};"
        : "+f"(c[0]), "+f"(c[1]), "+f"(c[2]), "+f"(c[3])
        : "r"(a[0]), "r"(a[1]), "r"(a[2]), "r"(a[3]), "r"(b0), "r"(b1));
}

static __device__ __forceinline__ void ldsm4(uint32_t& r0, uint32_t& r1,
                                             uint32_t& r2, uint32_t& r3, uint32_t saddr) {
    asm volatile("ldmatrix.sync.aligned.m8n8.x4.shared.b16 {%0,%1,%2,%3}, [%4];"
                 : "=r"(r0), "=r"(r1), "=r"(r2), "=r"(r3) : "r"(saddr));
}

static __device__ __forceinline__ void bulk_g2s(uint32_t dst, const void* src,
                                                uint32_t bytes, uint32_t mbar) {
    asm volatile(
        "cp.async.bulk.shared::cta.global.mbarrier::complete_tx::bytes [%0], [%1], %2, [%3];"
        :: "r"(dst), "l"(src), "r"(bytes), "r"(mbar) : "memory");
}

static __device__ __forceinline__ void mbar_expect(uint32_t mbar, uint32_t bytes) {
    asm volatile("mbarrier.arrive.expect_tx.shared.b64 _, [%0], %1;"
                 :: "r"(mbar), "r"(bytes) : "memory");
}

static __device__ __forceinline__ void mbar_wait(uint32_t mbar, uint32_t parity) {
    asm volatile(
        "{\n\t.reg .pred P1;\n\t"
        "WL_%=:\n\t"
        "mbarrier.try_wait.parity.acquire.cta.shared::cta.b64 P1, [%0], %1, 0x989680;\n\t"
        "@P1 bra.uni WD_%=;\n\t"
        "bra.uni WL_%=;\n\t"
        "WD_%=:\n\t}"
        :: "r"(mbar), "r"(parity) : "memory");
}

static __device__ __forceinline__ float sigmoidf_(float v) {
    return 1.0f / (1.0f + expf(-v));
}

// accurate recompute of t near threshold (A stored fp16 hi+lo, residual ~2^-24)
static __device__ __noinline__ float recompute_t(const uint32_t* AHrow, const uint32_t* ALrow,
                                                 const float* __restrict__ wt,
                                                 const float* __restrict__ wr) {
    float s = 0.0f;
    for (int k2 = 0; k2 < 64; k2++) {
        __half2 uh = *reinterpret_cast<const __half2*>(&AHrow[k2]);
        __half2 ul = *reinterpret_cast<const __half2*>(&ALrow[k2]);
        float a0 = __half2float(__low2half(uh)) + __half2float(__low2half(ul));
        float a1 = __half2float(__high2half(uh)) + __half2float(__high2half(ul));
        s += a0 * wt[2 * k2] + a1 * wt[2 * k2 + 1];
    }
    for (int k2 = 64; k2 < 128; k2++) {
        __half2 uh = *reinterpret_cast<const __half2*>(&AHrow[k2]);
        __half2 ul = *reinterpret_cast<const __half2*>(&ALrow[k2]);
        float a0 = __half2float(__low2half(uh)) + __half2float(__low2half(ul));
        float a1 = __half2float(__high2half(uh)) + __half2float(__high2half(ul));
        s += a0 * wr[2 * k2 - 128] + a1 * wr[2 * k2 - 127];
    }
    return s;
}

// ---------------- weight pre-split (de-interleaved, chunk-major padded) ----------------
// layer cols: [0, HC) = x-gate (Wl/Wr row j=c), [HC, 2HC) = t-gate (Wlt/Wrt row j=c-HC)
// k < 128 -> self weights, k >= 128 -> neigh weights.
__global__ void presplit(const float* __restrict__ Wl1, const float* __restrict__ Wr1,
                         const float* __restrict__ Wlt1, const float* __restrict__ Wrt1,
                         const float* __restrict__ Wl2, const float* __restrict__ Wr2,
                         const float* __restrict__ Wlt2, const float* __restrict__ Wrt2) {
    int c = blockIdx.x;          // 0..383
    int t = threadIdx.x;         // 0..127 -> k pair (2t, 2t+1)
    bool is1 = c < 256;
    int cc = is1 ? c : c - 256;
    int ncol = is1 ? 256 : 128;
    int hc = ncol >> 1;
    bool isT = cc >= hc;
    int j = isT ? cc - hc : cc;
    int k = 2 * t;
    const float* base;
    if (is1) base = (k < 128) ? (isT ? Wlt1 : Wl1) : (isT ? Wrt1 : Wr1);
    else     base = (k < 128) ? (isT ? Wlt2 : Wl2) : (isT ? Wrt2 : Wr2);
    int kk = k & 127;
    float x = base[j * 128 + kk], y = base[j * 128 + kk + 1];
    uint32_t ph, pl;
    split2h(x, y, ph, pl);
    int chunk = t >> 4, p = t & 15;
    long idx = ((long)chunk * ncol + cc) * 20 + p;
    if (is1) { g_B1h[idx] = ph; g_B1l[idx] = pl; }
    else     { g_B2h[idx] = ph; g_B2l[idx] = pl; }
}

// ---------------- fused GEMM + epilogue ----------------
#define AP 132   // uint32 per A row (128 data + 4 pad) -> 528B row stride
#define BP 20    // uint32 per B col per 32-k chunk -> 80B col stride

template <bool L1>
__global__ void __launch_bounds__(512, 1)
signn_gemm(const float* __restrict__ h0, const float* __restrict__ h1,
           const float* __restrict__ h2,
           const float* __restrict__ Wt_self, const float* __restrict__ Wt_neigh,
           float* __restrict__ outp, int N)
{
    constexpr int NCOL = L1 ? 256 : 128;
    constexpr int HC   = NCOL / 2;       // x/t half size in cols
    constexpr int NXTW = HC / 8 / 4;     // x-tiles per warp (l1:4, l2:2)
    constexpr int NXP  = NXTW / 2;       // ldsm pairs per half (l1:2, l2:1)
    constexpr int OC   = L1 ? 128 : 64;  // output features
    constexpr uint32_t SRC_CHUNK = NCOL * BP;             // u32 per chunk in gmem
    constexpr uint32_t BH_B = NCOL * BP * 4;              // hi bytes per chunk
    constexpr uint32_t BL_B = L1 ? (HC * BP * 4) : 0;     // lo bytes (x-half only; l2 none)
    constexpr uint32_t BUF_B = BH_B + BL_B;

    extern __shared__ uint32_t sm[];
    uint32_t* AH = sm;
    uint32_t* AL = sm + 128 * AP;
    uint32_t* Bb = sm + 2 * 128 * AP;                 // 2 buffers x (bh | bl)
    uint32_t* mbars = Bb + 2 * (BUF_B / 4);

    const int tid = threadIdx.x;
    const int w = tid >> 5, l = tid & 31;
    const int g = l >> 2, tg = l & 3;
    const int warpM = w >> 2, warpN = w & 3;
    const long rows = L1 ? 6L * N : (long)N;
    const long blockRow = (long)blockIdx.x * 128;
    const uint32_t* Bh = L1 ? g_B1h : g_B2h;
    const uint32_t* Bl = L1 ? g_B1l : g_B2l;
    float* op = L1 ? g_outs : outp;

    const uint32_t mb0 = (uint32_t)__cvta_generic_to_shared(mbars);
    const uint32_t mb1 = mb0 + 8;
    const uint32_t bBase = (uint32_t)__cvta_generic_to_shared(Bb);

    // ldmatrix lane geometry
    const int rowA = l & 15;
    const int kofA = (l >= 16) ? 8 : 0;
    const int nofB = (l & 7) + ((l >= 16) ? 8 : 0);
    const int kofB = (l & 8) ? 8 : 0;

    if (tid == 0) {
        asm volatile("mbarrier.init.shared.b64 [%0], 1;" :: "r"(mb0) : "memory");
        asm volatile("mbarrier.init.shared.b64 [%0], 1;" :: "r"(mb1) : "memory");
    }
    __syncthreads();

    // ---- kick off bulk prefetch of chunks 0 and 1 ----
    if (tid == 0) {
        mbar_expect(mb0, BUF_B);
        bulk_g2s(bBase, Bh + 0 * SRC_CHUNK, BH_B, mb0);
        if (L1) bulk_g2s(bBase + BH_B, Bl + 0 * SRC_CHUNK, BL_B, mb0);
        mbar_expect(mb1, BUF_B);
        bulk_g2s(bBase + BUF_B, Bh + 1 * SRC_CHUNK, BH_B, mb1);
        if (L1) bulk_g2s(bBase + BUF_B + BH_B, Bl + 1 * SRC_CHUNK, BL_B, mb1);
    }

    // ---- stage A: gather rows, split to fp16 hi/lo ----
#pragma unroll
    for (int rr = 0; rr < 8; rr++) {
        int row = w * 8 + rr;
        long gr = blockRow + row;
        long grc = gr < rows ? gr : rows - 1;
        float4 xv, nv;
        if (L1) {
            if (grc < N) {
                xv = ((const float4*)h0)[grc * 32 + l];
                const float4* p = (const float4*)h1 + grc * 5 * 32 + l;
                float4 a0 = p[0], a1 = p[32], a2 = p[64], a3 = p[96], a4 = p[128];
                nv.x = (a0.x + a1.x + a2.x + a3.x + a4.x) * 0.2f;
                nv.y = (a0.y + a1.y + a2.y + a3.y + a4.y) * 0.2f;
                nv.z = (a0.z + a1.z + a2.z + a3.z + a4.z) * 0.2f;
                nv.w = (a0.w + a1.w + a2.w + a3.w + a4.w) * 0.2f;
            } else {
                long q = grc - N;
                xv = ((const float4*)h1)[q * 32 + l];
                const float4* p = (const float4*)h2 + q * 2 * 32 + l;
                float4 a0 = p[0], a1 = p[32];
                nv.x = (a0.x + a1.x) * 0.5f;
                nv.y = (a0.y + a1.y) * 0.5f;
                nv.z = (a0.z + a1.z) * 0.5f;
                nv.w = (a0.w + a1.w) * 0.5f;
            }
        } else {
            xv = ((const float4*)g_outs)[grc * 32 + l];
            const float4* p = (const float4*)g_outs + ((long)N + grc * 5) * 32 + l;
            float4 a0 = p[0], a1 = p[32], a2 = p[64], a3 = p[96], a4 = p[128];
            nv.x = (a0.x + a1.x + a2.x + a3.x + a4.x) * 0.2f;
            nv.y = (a0.y + a1.y + a2.y + a3.y + a4.y) * 0.2f;
            nv.z = (a0.z + a1.z + a2.z + a3.z + a4.z) * 0.2f;
            nv.w = (a0.w + a1.w + a2.w + a3.w + a4.w) * 0.2f;
        }
        uint32_t h0p, l0p, h1p, l1p;
        split2h(xv.x, xv.y, h0p, l0p);
        split2h(xv.z, xv.w, h1p, l1p);
        *(uint2*)&AH[row * AP + 2 * l] = make_uint2(h0p, h1p);
        *(uint2*)&AL[row * AP + 2 * l] = make_uint2(l0p, l1p);
        split2h(nv.x, nv.y, h0p, l0p);
        split2h(nv.z, nv.w, h1p, l1p);
        *(uint2*)&AH[row * AP + 64 + 2 * l] = make_uint2(h0p, h1p);
        *(uint2*)&AL[row * AP + 64 + 2 * l] = make_uint2(l0p, l1p);
    }
    __syncthreads();   // A visible to all warps

    float accx[2][NXTW][4], acct[2][NXTW][4];
#pragma unroll
    for (int mt = 0; mt < 2; mt++)
#pragma unroll
        for (int nt = 0; nt < NXTW; nt++)
#pragma unroll
            for (int e = 0; e < 4; e++) { accx[mt][nt][e] = 0.0f; acct[mt][nt][e] = 0.0f; }

    const uint32_t aHbase = (uint32_t)__cvta_generic_to_shared(AH);
    const uint32_t aLbase = (uint32_t)__cvta_generic_to_shared(AL);

    // ---- main loop: 8 chunks of BK=32 ----
#pragma unroll 1
    for (int kc = 0; kc < 8; kc++) {
        const int b = kc & 1;
        const uint32_t mbb = b ? mb1 : mb0;
        mbar_wait(mbb, (kc >> 1) & 1);

        const uint32_t bHc = bBase + b * BUF_B;          // hi: all NCOL cols
        const uint32_t bLc = bHc + BH_B;                 // lo: x-half cols only
#pragma unroll
        for (int ks = 0; ks < 2; ks++) {
            int kb = kc * 32 + ks * 16;
            uint32_t ah[2][4], al[2][4];
#pragma unroll
            for (int mt = 0; mt < 2; mt++) {
                uint32_t ro = (uint32_t)(warpM * 32 + mt * 16 + rowA) * (AP * 4)
                            + (kb + kofA) * 2;
                ldsm4(ah[mt][0], ah[mt][1], ah[mt][2], ah[mt][3], aHbase + ro);
                ldsm4(al[mt][0], al[mt][1], al[mt][2], al[mt][3], aLbase + ro);
            }
#pragma unroll
            for (int ntp = 0; ntp < NXP; ntp++) {
                int xcol = warpN * (NXTW * 8) + ntp * 16 + nofB;     // x-half col
                uint32_t koff = (uint32_t)(ks * 16 + kofB) * 2;
                // ---- x-gate: 3 terms (hh, hl, lh) ----
                uint32_t bh[4], bl[4];
                ldsm4(bh[0], bh[1], bh[2], bh[3], bHc + (uint32_t)xcol * 80 + koff);
                ldsm4(bl[0], bl[1], bl[2], bl[3], bLc + (uint32_t)xcol * 80 + koff);
#pragma unroll
                for (int tile = 0; tile < 2; tile++) {
                    int nt = ntp * 2 + tile;
#pragma unroll
                    for (int mt = 0; mt < 2; mt++) {
                        mma16(accx[mt][nt], ah[mt], bh[2 * tile], bh[2 * tile + 1]);
                        if (L1)
                            mma16(accx[mt][nt], ah[mt], bl[2 * tile], bl[2 * tile + 1]);
                        mma16(accx[mt][nt], al[mt], bh[2 * tile], bh[2 * tile + 1]);
                    }
                }
                // ---- t-gate: 1 term (hh) ----
                uint32_t bt[4];
                ldsm4(bt[0], bt[1], bt[2], bt[3],
                      bHc + (uint32_t)(HC + xcol) * 80 + koff);
#pragma unroll
                for (int tile = 0; tile < 2; tile++) {
                    int nt = ntp * 2 + tile;
#pragma unroll
                    for (int mt = 0; mt < 2; mt++)
                        mma16(acct[mt][nt], ah[mt], bt[2 * tile], bt[2 * tile + 1]);
                }
            }
        }

        if (kc + 2 < 8) {
            __syncthreads();
            if (tid == 0) {
                mbar_expect(mbb, BUF_B);
                bulk_g2s(bBase + b * BUF_B, Bh + (kc + 2) * SRC_CHUNK, BH_B, mbb);
                if (L1) bulk_g2s(bBase + b * BUF_B + BH_B,
                                 Bl + (kc + 2) * SRC_CHUNK, BL_B, mbb);
            }
        }
    }

    // ---- epilogue: out = sigmoid(x) * spike(t), guarded near threshold ----
#pragma unroll
    for (int mt = 0; mt < 2; mt++) {
#pragma unroll
        for (int nt = 0; nt < NXTW; nt++) {
            int j0 = (warpN * NXTW + nt) * 8 + tg * 2;
#pragma unroll
            for (int half = 0; half < 2; half++) {
                int rloc = warpM * 32 + mt * 16 + g + half * 8;
                long gr = blockRow + rloc;
                if (gr < rows) {
#pragma unroll
                    for (int e = 0; e < 2; e++) {
                        int j = j0 + e;
                        float x = accx[mt][nt][half * 2 + e];
                        float t = acct[mt][nt][half * 2 + e];
                        if (fabsf(t - 1.0f) < 1.5e-3f)
                            t = recompute_t(&AH[rloc * AP], &AL[rloc * AP],
                                            Wt_self + j * 128, Wt_neigh + j * 128);
                        op[gr * OC + j] = (t >= 1.0f) ? sigmoidf_(x) : 0.0f;
                    }
                }
            }
        }
    }
}

extern "C" void kernel_launch(void* const* d_in, const int* in_sizes, int n_in,
                              void* d_out, int out_size)
{
    const float* h0   = (const float*)d_in[0];
    const float* h1   = (const float*)d_in[1];
    const float* h2   = (const float*)d_in[2];
    const float* Wl1  = (const float*)d_in[3];
    const float* Wr1  = (const float*)d_in[4];
    const float* Wlt1 = (const float*)d_in[5];
    const float* Wrt1 = (const float*)d_in[6];
    const float* Wl2  = (const float*)d_in[7];
    const float* Wr2  = (const float*)d_in[8];
    const float* Wlt2 = (const float*)d_in[9];
    const float* Wrt2 = (const float*)d_in[10];

    int N = in_sizes[0] / 128;

    int smem1 = 2 * 128 * AP * 4 + 2 * (256 * BP * 4 + 128 * BP * 4) + 64; // ~197KB
    int smem2 = 2 * 128 * AP * 4 + 2 * (128 * BP * 4) + 64;                // ~156KB
    cudaFuncSetAttribute(signn_gemm<true>,  cudaFuncAttributeMaxDynamicSharedMemorySize, smem1);
    cudaFuncSetAttribute(signn_gemm<false>, cudaFuncAttributeMaxDynamicSharedMemorySize, smem2);

    long rows = 6L * N;
    int grid1 = (int)((rows + 127) / 128);
    int grid2 = (N + 127) / 128;

    presplit<<<384, 128>>>(Wl1, Wr1, Wlt1, Wrt1, Wl2, Wr2, Wlt2, Wrt2);
    signn_gemm<true><<<grid1, 512, smem1>>>(h0, h1, h2, Wlt1, Wrt1, nullptr, N);
    signn_gemm<false><<<grid2, 512, smem2>>>(nullptr, nullptr, nullptr, Wlt2, Wrt2,
                                             (float*)d_out, N);
}

// round 11
// speedup vs baseline: 1.2710x; 1.0115x over previous
#include <cuda_runtime.h>
#include <cuda_fp16.h>
#include <math.h>
#include <stdint.h>

// ---------------- global scratch ----------------
__device__ float    g_outs[76800000];     // layer-1 out_s: 600000 x 128 (fp32)
// B weights, pre-split fp16 hi/lo, DE-INTERLEAVED (x cols then t cols),
// chunk16-major padded: [chunk(16)][col][12 u32] (8 u32 = 16 k packed half2 + 4 pad)
__device__ uint32_t g_B1h[16 * 256 * 12], g_B1l[16 * 256 * 12];
__device__ uint32_t g_B2h[16 * 128 * 12], g_B2l[16 * 128 * 12];

// ---------------- helpers ----------------
static __device__ __forceinline__ void split2h(float x, float y, uint32_t& ph, uint32_t& pl) {
    __half hx = __float2half(x);
    __half hy = __float2half(y);
    float rx = x - __half2float(hx);
    float ry = y - __half2float(hy);
    __half2 H = __halves2half2(hx, hy);
    __half2 L = __halves2half2(__float2half(rx), __float2half(ry));
    ph = *reinterpret_cast<uint32_t*>(&H);
    pl = *reinterpret_cast<uint32_t*>(&L);
}

static __device__ __forceinline__ void mma16(float c[4], const uint32_t a[4],
                                             uint32_t b0, uint32_t b1) {
    asm volatile(
        "mma.sync.aligned.m16n8k16.row.col.f32.f16.f16.f32 "
        "{%0,%1,%2,%3}, {%4,%5,%6,%7}, {%8,%9}, {%0,%1,%2,%3};"
        : "+f"(c[0]), "+f"(c[1]), "+f"(c[2]), "+f"(c[3])
        : "r"(a[0]), "r"(a[1]), "r"(a[2]), "r"(a[3]), "r"(b0), "r"(b1));
}

static __device__ __forceinline__ void ldsm4(uint32_t& r0, uint32_t& r1,
                                             uint32_t& r2, uint32_t& r3, uint32_t saddr) {
    asm volatile("ldmatrix.sync.aligned.m8n8.x4.shared.b16 {%0,%1,%2,%3}, [%4];"
                 : "=r"(r0), "=r"(r1), "=r"(r2), "=r"(r3) : "r"(saddr));
}

static __device__ __forceinline__ void bulk_g2s(uint32_t dst, const void* src,
                                                uint32_t bytes, uint32_t mbar) {
    asm volatile(
        "cp.async.bulk.shared::cta.global.mbarrier::complete_tx::bytes [%0], [%1], %2, [%3];"
        :: "r"(dst), "l"(src), "r"(bytes), "r"(mbar) : "memory");
}

static __device__ __forceinline__ void mbar_expect(uint32_t mbar, uint32_t bytes) {
    asm volatile("mbarrier.arrive.expect_tx.shared.b64 _, [%0], %1;"
                 :: "r"(mbar), "r"(bytes) : "memory");
}

static __device__ __forceinline__ void mbar_wait(uint32_t mbar, uint32_t parity) {
    asm volatile(
        "{\n\t.reg .pred P1;\n\t"
        "WL_%=:\n\t"
        "mbarrier.try_wait.parity.acquire.cta.shared::cta.b64 P1, [%0], %1, 0x989680;\n\t"
        "@P1 bra.uni WD_%=;\n\t"
        "bra.uni WL_%=;\n\t"
        "WD_%=:\n\t}"
        :: "r"(mbar), "r"(parity) : "memory");
}

static __device__ __forceinline__ float sigmoidf_(float v) {
    return 1.0f / (1.0f + expf(-v));
}

// accurate recompute of t near threshold (A stored fp16 hi+lo, residual ~2^-24)
static __device__ __noinline__ float recompute_t(const uint32_t* AHrow, const uint32_t* ALrow,
                                                 const float* __restrict__ wt,
                                                 const float* __restrict__ wr) {
    float s = 0.0f;
    for (int k2 = 0; k2 < 64; k2++) {
        __half2 uh = *reinterpret_cast<const __half2*>(&AHrow[k2]);
        __half2 ul = *reinterpret_cast<const __half2*>(&ALrow[k2]);
        float a0 = __half2float(__low2half(uh)) + __half2float(__low2half(ul));
        float a1 = __half2float(__high2half(uh)) + __half2float(__high2half(ul));
        s += a0 * wt[2 * k2] + a1 * wt[2 * k2 + 1];
    }
    for (int k2 = 64; k2 < 128; k2++) {
        __half2 uh = *reinterpret_cast<const __half2*>(&AHrow[k2]);
        __half2 ul = *reinterpret_cast<const __half2*>(&ALrow[k2]);
        float a0 = __half2float(__low2half(uh)) + __half2float(__low2half(ul));
        float a1 = __half2float(__high2half(uh)) + __half2float(__high2half(ul));
        s += a0 * wr[2 * k2 - 128] + a1 * wr[2 * k2 - 127];
    }
    return s;
}

// ---------------- weight pre-split (de-interleaved, chunk16-major, 48B stride) ----------------
// layer cols: [0, HC) = x-gate (Wl/Wr row j=c), [HC, 2HC) = t-gate (Wlt/Wrt row j=c-HC)
// k < 128 -> self weights, k >= 128 -> neigh weights.
__global__ void presplit(const float* __restrict__ Wl1, const float* __restrict__ Wr1,
                         const float* __restrict__ Wlt1, const float* __restrict__ Wrt1,
                         const float* __restrict__ Wl2, const float* __restrict__ Wr2,
                         const float* __restrict__ Wlt2, const float* __restrict__ Wrt2) {
    int c = blockIdx.x;          // 0..383
    int t = threadIdx.x;         // 0..127 -> k pair (2t, 2t+1)
    bool is1 = c < 256;
    int cc = is1 ? c : c - 256;
    int ncol = is1 ? 256 : 128;
    int hc = ncol >> 1;
    bool isT = cc >= hc;
    int j = isT ? cc - hc : cc;
    int k = 2 * t;
    const float* base;
    if (is1) base = (k < 128) ? (isT ? Wlt1 : Wl1) : (isT ? Wrt1 : Wr1);
    else     base = (k < 128) ? (isT ? Wlt2 : Wl2) : (isT ? Wrt2 : Wr2);
    int kk = k & 127;
    float x = base[j * 128 + kk], y = base[j * 128 + kk + 1];
    uint32_t ph, pl;
    split2h(x, y, ph, pl);
    int chunk = t >> 3, p = t & 7;      // 16k chunks, 8 u32 data per col
    long idx = ((long)chunk * ncol + cc) * 12 + p;
    if (is1) { g_B1h[idx] = ph; g_B1l[idx] = pl; }
    else     { g_B2h[idx] = ph; g_B2l[idx] = pl; }
}

// ---------------- fused GEMM + epilogue (BM=64, 256 thr, 2 CTAs/SM) ----------------
#define AP 132   // uint32 per A row (128 data + 4 pad) -> 528B row stride
#define BPC 12   // uint32 per B col per 16-k chunk -> 48B col stride (16B-aligned!)

template <bool L1>
__global__ void __launch_bounds__(256, 2)
signn_gemm(const float* __restrict__ h0, const float* __restrict__ h1,
           const float* __restrict__ h2,
           const float* __restrict__ Wt_self, const float* __restrict__ Wt_neigh,
           float* __restrict__ outp, int N)
{
    constexpr int NCOL = L1 ? 256 : 128;
    constexpr int HC   = NCOL / 2;        // x/t half size in cols
    constexpr int NXTW = HC / 2 / 8;      // x-tiles per warp (l1:8, l2:4)
    constexpr int NXP  = NXTW / 2;        // ldsm 16-col pairs (l1:4, l2:2)
    constexpr int OC   = L1 ? 128 : 64;   // output features
    constexpr uint32_t SRC_CHUNK = NCOL * BPC;            // u32 per chunk in gmem
    constexpr uint32_t BH_B = NCOL * BPC * 4;             // hi bytes per chunk
    constexpr uint32_t BL_B = L1 ? (HC * BPC * 4) : 0;    // lo bytes (x-half only)
    constexpr uint32_t BUF_B = BH_B + BL_B;

    extern __shared__ uint32_t sm[];
    uint32_t* AH = sm;                        // 64 x AP
    uint32_t* AL = sm + 64 * AP;
    uint32_t* Bb = sm + 2 * 64 * AP;          // 2 buffers x (bh | bl)
    uint32_t* mbars = Bb + 2 * (BUF_B / 4);

    const int tid = threadIdx.x;
    const int w = tid >> 5, l = tid & 31;     // 8 warps
    const int g = l >> 2, tg = l & 3;
    const int warpM = w >> 1, warpN = w & 1;  // 4 m x 2 n
    const long rows = L1 ? 6L * N : (long)N;
    const long blockRow = (long)blockIdx.x * 64;
    const uint32_t* Bh = L1 ? g_B1h : g_B2h;
    const uint32_t* Bl = L1 ? g_B1l : g_B2l;
    float* op = L1 ? g_outs : outp;

    const uint32_t mb0 = (uint32_t)__cvta_generic_to_shared(mbars);
    const uint32_t mb1 = mb0 + 8;
    const uint32_t bBase = (uint32_t)__cvta_generic_to_shared(Bb);

    // ldmatrix lane geometry
    const int rowA = l & 15;
    const int kofA = (l >= 16) ? 8 : 0;
    const int nofB = (l & 7) + ((l >= 16) ? 8 : 0);
    const int kofB = (l & 8) ? 8 : 0;

    if (tid == 0) {
        asm volatile("mbarrier.init.shared.b64 [%0], 1;" :: "r"(mb0) : "memory");
        asm volatile("mbarrier.init.shared.b64 [%0], 1;" :: "r"(mb1) : "memory");
    }
    __syncthreads();

    // ---- kick off bulk prefetch of chunks 0 and 1 ----
    if (tid == 0) {
        mbar_expect(mb0, BUF_B);
        bulk_g2s(bBase, Bh + 0 * SRC_CHUNK, BH_B, mb0);
        if (L1) bulk_g2s(bBase + BH_B, Bl + 0 * SRC_CHUNK, BL_B, mb0);
        mbar_expect(mb1, BUF_B);
        bulk_g2s(bBase + BUF_B, Bh + 1 * SRC_CHUNK, BH_B, mb1);
        if (L1) bulk_g2s(bBase + BUF_B + BH_B, Bl + 1 * SRC_CHUNK, BL_B, mb1);
    }

    // ---- stage A: 64 rows, gather + split to fp16 hi/lo ----
#pragma unroll
    for (int rr = 0; rr < 8; rr++) {
        int row = w * 8 + rr;
        long gr = blockRow + row;
        long grc = gr < rows ? gr : rows - 1;
        float4 xv, nv;
        if (L1) {
            if (grc < N) {
                xv = ((const float4*)h0)[grc * 32 + l];
                const float4* p = (const float4*)h1 + grc * 5 * 32 + l;
                float4 a0 = p[0], a1 = p[32], a2 = p[64], a3 = p[96], a4 = p[128];
                nv.x = (a0.x + a1.x + a2.x + a3.x + a4.x) * 0.2f;
                nv.y = (a0.y + a1.y + a2.y + a3.y + a4.y) * 0.2f;
                nv.z = (a0.z + a1.z + a2.z + a3.z + a4.z) * 0.2f;
                nv.w = (a0.w + a1.w + a2.w + a3.w + a4.w) * 0.2f;
            } else {
                long q = grc - N;
                xv = ((const float4*)h1)[q * 32 + l];
                const float4* p = (const float4*)h2 + q * 2 * 32 + l;
                float4 a0 = p[0], a1 = p[32];
                nv.x = (a0.x + a1.x) * 0.5f;
                nv.y = (a0.y + a1.y) * 0.5f;
                nv.z = (a0.z + a1.z) * 0.5f;
                nv.w = (a0.w + a1.w) * 0.5f;
            }
        } else {
            xv = ((const float4*)g_outs)[grc * 32 + l];
            const float4* p = (const float4*)g_outs + ((long)N + grc * 5) * 32 + l;
            float4 a0 = p[0], a1 = p[32], a2 = p[64], a3 = p[96], a4 = p[128];
            nv.x = (a0.x + a1.x + a2.x + a3.x + a4.x) * 0.2f;
            nv.y = (a0.y + a1.y + a2.y + a3.y + a4.y) * 0.2f;
            nv.z = (a0.z + a1.z + a2.z + a3.z + a4.z) * 0.2f;
            nv.w = (a0.w + a1.w + a2.w + a3.w + a4.w) * 0.2f;
        }
        uint32_t h0p, l0p, h1p, l1p;
        split2h(xv.x, xv.y, h0p, l0p);
        split2h(xv.z, xv.w, h1p, l1p);
        *(uint2*)&AH[row * AP + 2 * l] = make_uint2(h0p, h1p);
        *(uint2*)&AL[row * AP + 2 * l] = make_uint2(l0p, l1p);
        split2h(nv.x, nv.y, h0p, l0p);
        split2h(nv.z, nv.w, h1p, l1p);
        *(uint2*)&AH[row * AP + 64 + 2 * l] = make_uint2(h0p, h1p);
        *(uint2*)&AL[row * AP + 64 + 2 * l] = make_uint2(l0p, l1p);
    }
    __syncthreads();   // A visible to all warps

    float accx[NXTW][4], acct[NXTW][4];
#pragma unroll
    for (int nt = 0; nt < NXTW; nt++)
#pragma unroll
        for (int e = 0; e < 4; e++) { accx[nt][e] = 0.0f; acct[nt][e] = 0.0f; }

    const uint32_t aHbase = (uint32_t)__cvta_generic_to_shared(AH);
    const uint32_t aLbase = (uint32_t)__cvta_generic_to_shared(AL);

    // ---- main loop: 16 chunks of BK=16, double-buffered bulk DMA ----
#pragma unroll 1
    for (int kc = 0; kc < 16; kc++) {
        const int b = kc & 1;
        const uint32_t mbb = b ? mb1 : mb0;
        mbar_wait(mbb, (kc >> 1) & 1);

        const uint32_t bHc = bBase + b * BUF_B;          // hi: all NCOL cols
        const uint32_t bLc = bHc + BH_B;                 // lo: x-half cols only
        const int kb = kc * 16;

        uint32_t ah[4], al[4];
        {
            uint32_t ro = (uint32_t)(warpM * 16 + rowA) * (AP * 4) + (kb + kofA) * 2;
            ldsm4(ah[0], ah[1], ah[2], ah[3], aHbase + ro);
            ldsm4(al[0], al[1], al[2], al[3], aLbase + ro);
        }
#pragma unroll
        for (int ntp = 0; ntp < NXP; ntp++) {
            int xcol = warpN * (NXTW * 8) + ntp * 16 + nofB;
            uint32_t koff = (uint32_t)kofB * 2;
            // ---- x-gate ----
            uint32_t bh[4], bl[4];
            ldsm4(bh[0], bh[1], bh[2], bh[3], bHc + (uint32_t)xcol * 48 + koff);
            if (L1)
                ldsm4(bl[0], bl[1], bl[2], bl[3], bLc + (uint32_t)xcol * 48 + koff);
#pragma unroll
            for (int tile = 0; tile < 2; tile++) {
                int nt = ntp * 2 + tile;
                mma16(accx[nt], ah, bh[2 * tile], bh[2 * tile + 1]);
                if (L1)
                    mma16(accx[nt], ah, bl[2 * tile], bl[2 * tile + 1]);
                mma16(accx[nt], al, bh[2 * tile], bh[2 * tile + 1]);
            }
            // ---- t-gate: 1 term ----
            uint32_t bt[4];
            ldsm4(bt[0], bt[1], bt[2], bt[3],
                  bHc + (uint32_t)(HC + xcol) * 48 + koff);
#pragma unroll
            for (int tile = 0; tile < 2; tile++)
                mma16(acct[ntp * 2 + tile], ah, bt[2 * tile], bt[2 * tile + 1]);
        }

        if (kc + 2 < 16) {
            __syncthreads();   // all warps done reading buffer b for chunk kc
            if (tid == 0) {
                mbar_expect(mbb, BUF_B);
                bulk_g2s(bBase + b * BUF_B, Bh + (kc + 2) * SRC_CHUNK, BH_B, mbb);
                if (L1) bulk_g2s(bBase + b * BUF_B + BH_B,
                                 Bl + (kc + 2) * SRC_CHUNK, BL_B, mbb);
            }
        }
    }

    // ---- epilogue: out = sigmoid(x) * spike(t), guarded near threshold ----
#pragma unroll
    for (int nt = 0; nt < NXTW; nt++) {
        int j0 = warpN * (NXTW * 8) + nt * 8 + tg * 2;
#pragma unroll
        for (int half = 0; half < 2; half++) {
            int rloc = warpM * 16 + g + half * 8;
            long gr = blockRow + rloc;
            if (gr < rows) {
#pragma unroll
                for (int e = 0; e < 2; e++) {
                    int j = j0 + e;
                    float x = accx[nt][half * 2 + e];
                    float t = acct[nt][half * 2 + e];
                    if (fabsf(t - 1.0f) < 1.5e-3f)
                        t = recompute_t(&AH[rloc * AP], &AL[rloc * AP],
                                        Wt_self + j * 128, Wt_neigh + j * 128);
                    op[gr * OC + j] = (t >= 1.0f) ? sigmoidf_(x) : 0.0f;
                }
            }
        }
    }
}

extern "C" void kernel_launch(void* const* d_in, const int* in_sizes, int n_in,
                              void* d_out, int out_size)
{
    const float* h0   = (const float*)d_in[0];
    const float* h1   = (const float*)d_in[1];
    const float* h2   = (const float*)d_in[2];
    const float* Wl1  = (const float*)d_in[3];
    const float* Wr1  = (const float*)d_in[4];
    const float* Wlt1 = (const float*)d_in[5];
    const float* Wrt1 = (const float*)d_in[6];
    const float* Wl2  = (const float*)d_in[7];
    const float* Wr2  = (const float*)d_in[8];
    const float* Wlt2 = (const float*)d_in[9];
    const float* Wrt2 = (const float*)d_in[10];

    int N = in_sizes[0] / 128;

    int smem1 = 2 * 64 * AP * 4 + 2 * (256 * BPC * 4 + 128 * BPC * 4) + 64;  // 104,512 B
    int smem2 = 2 * 64 * AP * 4 + 2 * (128 * BPC * 4) + 64;                  //  79,936 B
    cudaFuncSetAttribute(signn_gemm<true>,  cudaFuncAttributeMaxDynamicSharedMemorySize, smem1);
    cudaFuncSetAttribute(signn_gemm<false>, cudaFuncAttributeMaxDynamicSharedMemorySize, smem2);

    long rows = 6L * N;
    int grid1 = (int)((rows + 63) / 64);
    int grid2 = (N + 63) / 64;

    presplit<<<384, 128>>>(Wl1, Wr1, Wlt1, Wrt1, Wl2, Wr2, Wlt2, Wrt2);
    signn_gemm<true><<<grid1, 256, smem1>>>(h0, h1, h2, Wlt1, Wrt1, nullptr, N);
    signn_gemm<false><<<grid2, 256, smem2>>>(nullptr, nullptr, nullptr, Wlt2, Wrt2,
                                             (float*)d_out, N);
}

// round 12
// speedup vs baseline: 1.3542x; 1.0654x over previous
#include <cuda_runtime.h>
#include <cuda_fp16.h>
#include <math.h>
#include <stdint.h>

// ---------------- global scratch ----------------
__device__ float    g_outs[76800000];     // layer-1 out_s: 600000 x 128 (fp32)
// B weights, pre-split fp16 hi/lo, DE-INTERLEAVED (x cols then t cols),
// chunk16-major padded: [chunk(16)][col][12 u32] (8 u32 = 16 k packed half2 + 4 pad)
__device__ uint32_t g_B1h[16 * 256 * 12], g_B1l[16 * 256 * 12];
__device__ uint32_t g_B2h[16 * 128 * 12], g_B2l[16 * 128 * 12];

// ---------------- helpers ----------------
static __device__ __forceinline__ void split2h(float x, float y, uint32_t& ph, uint32_t& pl) {
    __half hx = __float2half(x);
    __half hy = __float2half(y);
    float rx = x - __half2float(hx);
    float ry = y - __half2float(hy);
    __half2 H = __halves2half2(hx, hy);
    __half2 L = __halves2half2(__float2half(rx), __float2half(ry));
    ph = *reinterpret_cast<uint32_t*>(&H);
    pl = *reinterpret_cast<uint32_t*>(&L);
}

static __device__ __forceinline__ void mma16(float c[4], const uint32_t a[4],
                                             uint32_t b0, uint32_t b1) {
    asm volatile(
        "mma.sync.aligned.m16n8k16.row.col.f32.f16.f16.f32 "
        "{%0,%1,%2,%3}, {%4,%5,%6,%7}, {%8,%9}, {%0,%1,%2,%3};"
        : "+f"(c[0]), "+f"(c[1]), "+f"(c[2]), "+f"(c[3])
        : "r"(a[0]), "r"(a[1]), "r"(a[2]), "r"(a[3]), "r"(b0), "r"(b1));
}

static __device__ __forceinline__ void ldsm4(uint32_t& r0, uint32_t& r1,
                                             uint32_t& r2, uint32_t& r3, uint32_t saddr) {
    asm volatile("ldmatrix.sync.aligned.m8n8.x4.shared.b16 {%0,%1,%2,%3}, [%4];"
                 : "=r"(r0), "=r"(r1), "=r"(r2), "=r"(r3) : "r"(saddr));
}

static __device__ __forceinline__ void bulk_g2s(uint32_t dst, const void* src,
                                                uint32_t bytes, uint32_t mbar) {
    asm volatile(
        "cp.async.bulk.shared::cta.global.mbarrier::complete_tx::bytes [%0], [%1], %2, [%3];"
        :: "r"(dst), "l"(src), "r"(bytes), "r"(mbar) : "memory");
}

static __device__ __forceinline__ void mbar_expect(uint32_t mbar, uint32_t bytes) {
    asm volatile("mbarrier.arrive.expect_tx.shared.b64 _, [%0], %1;"
                 :: "r"(mbar), "r"(bytes) : "memory");
}

static __device__ __forceinline__ void mbar_wait(uint32_t mbar, uint32_t parity) {
    asm volatile(
        "{\n\t.reg .pred P1;\n\t"
        "WL_%=:\n\t"
        "mbarrier.try_wait.parity.acquire.cta.shared::cta.b64 P1, [%0], %1, 0x989680;\n\t"
        "@P1 bra.uni WD_%=;\n\t"
        "bra.uni WL_%=;\n\t"
        "WD_%=:\n\t}"
        :: "r"(mbar), "r"(parity) : "memory");
}

static __device__ __forceinline__ float sigmoidf_(float v) {
    return 1.0f / (1.0f + expf(-v));
}

// accurate recompute of t near threshold (A stored fp16 hi+lo, residual ~2^-24)
static __device__ __noinline__ float recompute_t(const uint32_t* AHrow, const uint32_t* ALrow,
                                                 const float* __restrict__ wt,
                                                 const float* __restrict__ wr) {
    float s = 0.0f;
    for (int k2 = 0; k2 < 64; k2++) {
        __half2 uh = *reinterpret_cast<const __half2*>(&AHrow[k2]);
        __half2 ul = *reinterpret_cast<const __half2*>(&ALrow[k2]);
        float a0 = __half2float(__low2half(uh)) + __half2float(__low2half(ul));
        float a1 = __half2float(__high2half(uh)) + __half2float(__high2half(ul));
        s += a0 * wt[2 * k2] + a1 * wt[2 * k2 + 1];
    }
    for (int k2 = 64; k2 < 128; k2++) {
        __half2 uh = *reinterpret_cast<const __half2*>(&AHrow[k2]);
        __half2 ul = *reinterpret_cast<const __half2*>(&ALrow[k2]);
        float a0 = __half2float(__low2half(uh)) + __half2float(__low2half(ul));
        float a1 = __half2float(__high2half(uh)) + __half2float(__high2half(ul));
        s += a0 * wr[2 * k2 - 128] + a1 * wr[2 * k2 - 127];
    }
    return s;
}

// ---------------- weight pre-split (de-interleaved, chunk16-major, 48B stride) ----------------
__global__ void presplit(const float* __restrict__ Wl1, const float* __restrict__ Wr1,
                         const float* __restrict__ Wlt1, const float* __restrict__ Wrt1,
                         const float* __restrict__ Wl2, const float* __restrict__ Wr2,
                         const float* __restrict__ Wlt2, const float* __restrict__ Wrt2) {
    int c = blockIdx.x;          // 0..383
    int t = threadIdx.x;         // 0..127 -> k pair (2t, 2t+1)
    bool is1 = c < 256;
    int cc = is1 ? c : c - 256;
    int ncol = is1 ? 256 : 128;
    int hc = ncol >> 1;
    bool isT = cc >= hc;
    int j = isT ? cc - hc : cc;
    int k = 2 * t;
    const float* base;
    if (is1) base = (k < 128) ? (isT ? Wlt1 : Wl1) : (isT ? Wrt1 : Wr1);
    else     base = (k < 128) ? (isT ? Wlt2 : Wl2) : (isT ? Wrt2 : Wr2);
    int kk = k & 127;
    float x = base[j * 128 + kk], y = base[j * 128 + kk + 1];
    uint32_t ph, pl;
    split2h(x, y, ph, pl);
    int chunk = t >> 3, p = t & 7;      // 16k chunks, 8 u32 data per col
    long idx = ((long)chunk * ncol + cc) * 12 + p;
    if (is1) { g_B1h[idx] = ph; g_B1l[idx] = pl; }
    else     { g_B2h[idx] = ph; g_B2l[idx] = pl; }
}

// ---------------- fused GEMM + epilogue (BM=32, 256 thr, 3 CTAs/SM) ----------------
#define AP 132   // uint32 per A row (128 data + 4 pad) -> 528B row stride
#define BPC 12   // uint32 per B col per 16-k chunk -> 48B col stride (16B-aligned)

template <bool L1>
__global__ void __launch_bounds__(256, 3)
signn_gemm(const float* __restrict__ h0, const float* __restrict__ h1,
           const float* __restrict__ h2,
           const float* __restrict__ Wt_self, const float* __restrict__ Wt_neigh,
           float* __restrict__ outp, int N)
{
    constexpr int NCOL = L1 ? 256 : 128;
    constexpr int HC   = NCOL / 2;        // x/t half size in cols
    constexpr int NXTW = HC / 4 / 8;      // x-tiles per warp (l1:4, l2:2)
    constexpr int NXP  = NXTW / 2;        // ldsm 16-col pairs (l1:2, l2:1)
    constexpr int OC   = L1 ? 128 : 64;   // output features
    constexpr uint32_t SRC_CHUNK = NCOL * BPC;            // u32 per chunk in gmem
    constexpr uint32_t BH_B = NCOL * BPC * 4;             // hi bytes per chunk
    constexpr uint32_t BL_B = L1 ? (HC * BPC * 4) : 0;    // lo bytes (x-half only)
    constexpr uint32_t BUF_B = BH_B + BL_B;

    extern __shared__ uint32_t sm[];
    uint32_t* AH = sm;                        // 32 x AP
    uint32_t* AL = sm + 32 * AP;
    uint32_t* Bb = sm + 2 * 32 * AP;          // 2 buffers x (bh | bl)
    uint32_t* mbars = Bb + 2 * (BUF_B / 4);

    const int tid = threadIdx.x;
    const int w = tid >> 5, l = tid & 31;     // 8 warps
    const int g = l >> 2, tg = l & 3;
    const int warpM = w >> 2, warpN = w & 3;  // 2 m x 4 n
    const long rows = L1 ? 6L * N : (long)N;
    const long blockRow = (long)blockIdx.x * 32;
    const uint32_t* Bh = L1 ? g_B1h : g_B2h;
    const uint32_t* Bl = L1 ? g_B1l : g_B2l;
    float* op = L1 ? g_outs : outp;

    const uint32_t mb0 = (uint32_t)__cvta_generic_to_shared(mbars);
    const uint32_t mb1 = mb0 + 8;
    const uint32_t bBase = (uint32_t)__cvta_generic_to_shared(Bb);

    // ldmatrix lane geometry
    const int rowA = l & 15;
    const int kofA = (l >= 16) ? 8 : 0;
    const int nofB = (l & 7) + ((l >= 16) ? 8 : 0);
    const int kofB = (l & 8) ? 8 : 0;

    if (tid == 0) {
        asm volatile("mbarrier.init.shared.b64 [%0], 1;" :: "r"(mb0) : "memory");
        asm volatile("mbarrier.init.shared.b64 [%0], 1;" :: "r"(mb1) : "memory");
    }
    __syncthreads();

    // ---- kick off bulk prefetch of chunks 0 and 1 ----
    if (tid == 0) {
        mbar_expect(mb0, BUF_B);
        bulk_g2s(bBase, Bh + 0 * SRC_CHUNK, BH_B, mb0);
        if (L1) bulk_g2s(bBase + BH_B, Bl + 0 * SRC_CHUNK, BL_B, mb0);
        mbar_expect(mb1, BUF_B);
        bulk_g2s(bBase + BUF_B, Bh + 1 * SRC_CHUNK, BH_B, mb1);
        if (L1) bulk_g2s(bBase + BUF_B + BH_B, Bl + 1 * SRC_CHUNK, BL_B, mb1);
    }

    // ---- stage A: 32 rows (4 per warp), gather + split to fp16 hi/lo ----
#pragma unroll
    for (int rr = 0; rr < 4; rr++) {
        int row = w * 4 + rr;
        long gr = blockRow + row;
        long grc = gr < rows ? gr : rows - 1;
        float4 xv, nv;
        if (L1) {
            if (grc < N) {
                xv = ((const float4*)h0)[grc * 32 + l];
                const float4* p = (const float4*)h1 + grc * 5 * 32 + l;
                float4 a0 = p[0], a1 = p[32], a2 = p[64], a3 = p[96], a4 = p[128];
                nv.x = (a0.x + a1.x + a2.x + a3.x + a4.x) * 0.2f;
                nv.y = (a0.y + a1.y + a2.y + a3.y + a4.y) * 0.2f;
                nv.z = (a0.z + a1.z + a2.z + a3.z + a4.z) * 0.2f;
                nv.w = (a0.w + a1.w + a2.w + a3.w + a4.w) * 0.2f;
            } else {
                long q = grc - N;
                xv = ((const float4*)h1)[q * 32 + l];
                const float4* p = (const float4*)h2 + q * 2 * 32 + l;
                float4 a0 = p[0], a1 = p[32];
                nv.x = (a0.x + a1.x) * 0.5f;
                nv.y = (a0.y + a1.y) * 0.5f;
                nv.z = (a0.z + a1.z) * 0.5f;
                nv.w = (a0.w + a1.w) * 0.5f;
            }
        } else {
            xv = ((const float4*)g_outs)[grc * 32 + l];
            const float4* p = (const float4*)g_outs + ((long)N + grc * 5) * 32 + l;
            float4 a0 = p[0], a1 = p[32], a2 = p[64], a3 = p[96], a4 = p[128];
            nv.x = (a0.x + a1.x + a2.x + a3.x + a4.x) * 0.2f;
            nv.y = (a0.y + a1.y + a2.y + a3.y + a4.y) * 0.2f;
            nv.z = (a0.z + a1.z + a2.z + a3.z + a4.z) * 0.2f;
            nv.w = (a0.w + a1.w + a2.w + a3.w + a4.w) * 0.2f;
        }
        uint32_t h0p, l0p, h1p, l1p;
        split2h(xv.x, xv.y, h0p, l0p);
        split2h(xv.z, xv.w, h1p, l1p);
        *(uint2*)&AH[row * AP + 2 * l] = make_uint2(h0p, h1p);
        *(uint2*)&AL[row * AP + 2 * l] = make_uint2(l0p, l1p);
        split2h(nv.x, nv.y, h0p, l0p);
        split2h(nv.z, nv.w, h1p, l1p);
        *(uint2*)&AH[row * AP + 64 + 2 * l] = make_uint2(h0p, h1p);
        *(uint2*)&AL[row * AP + 64 + 2 * l] = make_uint2(l0p, l1p);
    }
    __syncthreads();   // A visible to all warps

    float accx[NXTW][4], acct[NXTW][4];
#pragma unroll
    for (int nt = 0; nt < NXTW; nt++)
#pragma unroll
        for (int e = 0; e < 4; e++) { accx[nt][e] = 0.0f; acct[nt][e] = 0.0f; }

    const uint32_t aHbase = (uint32_t)__cvta_generic_to_shared(AH);
    const uint32_t aLbase = (uint32_t)__cvta_generic_to_shared(AL);

    // ---- main loop: 16 chunks of BK=16, double-buffered bulk DMA ----
#pragma unroll 1
    for (int kc = 0; kc < 16; kc++) {
        const int b = kc & 1;
        const uint32_t mbb = b ? mb1 : mb0;
        mbar_wait(mbb, (kc >> 1) & 1);

        const uint32_t bHc = bBase + b * BUF_B;          // hi: all NCOL cols
        const uint32_t bLc = bHc + BH_B;                 // lo: x-half cols only
        const int kb = kc * 16;

        uint32_t ah[4], al[4];
        {
            uint32_t ro = (uint32_t)(warpM * 16 + rowA) * (AP * 4) + (kb + kofA) * 2;
            ldsm4(ah[0], ah[1], ah[2], ah[3], aHbase + ro);
            ldsm4(al[0], al[1], al[2], al[3], aLbase + ro);
        }
#pragma unroll
        for (int ntp = 0; ntp < NXP; ntp++) {
            int xcol = warpN * (NXTW * 8) + ntp * 16 + nofB;
            uint32_t koff = (uint32_t)kofB * 2;
            // ---- x-gate ----
            uint32_t bh[4], bl[4];
            ldsm4(bh[0], bh[1], bh[2], bh[3], bHc + (uint32_t)xcol * 48 + koff);
            if (L1)
                ldsm4(bl[0], bl[1], bl[2], bl[3], bLc + (uint32_t)xcol * 48 + koff);
#pragma unroll
            for (int tile = 0; tile < 2; tile++) {
                int nt = ntp * 2 + tile;
                mma16(accx[nt], ah, bh[2 * tile], bh[2 * tile + 1]);
                if (L1)
                    mma16(accx[nt], ah, bl[2 * tile], bl[2 * tile + 1]);
                mma16(accx[nt], al, bh[2 * tile], bh[2 * tile + 1]);
            }
            // ---- t-gate: 1 term ----
            uint32_t bt[4];
            ldsm4(bt[0], bt[1], bt[2], bt[3],
                  bHc + (uint32_t)(HC + xcol) * 48 + koff);
#pragma unroll
            for (int tile = 0; tile < 2; tile++)
                mma16(acct[ntp * 2 + tile], ah, bt[2 * tile], bt[2 * tile + 1]);
        }

        if (kc + 2 < 16) {
            __syncthreads();   // all warps done reading buffer b for chunk kc
            if (tid == 0) {
                mbar_expect(mbb, BUF_B);
                bulk_g2s(bBase + b * BUF_B, Bh + (kc + 2) * SRC_CHUNK, BH_B, mbb);
                if (L1) bulk_g2s(bBase + b * BUF_B + BH_B,
                                 Bl + (kc + 2) * SRC_CHUNK, BL_B, mbb);
            }
        }
    }

    // ---- epilogue: out = sigmoid(x) * spike(t), guarded near threshold ----
#pragma unroll
    for (int nt = 0; nt < NXTW; nt++) {
        int j0 = warpN * (NXTW * 8) + nt * 8 + tg * 2;
#pragma unroll
        for (int half = 0; half < 2; half++) {
            int rloc = warpM * 16 + g + half * 8;
            long gr = blockRow + rloc;
            if (gr < rows) {
#pragma unroll
                for (int e = 0; e < 2; e++) {
                    int j = j0 + e;
                    float x = accx[nt][half * 2 + e];
                    float t = acct[nt][half * 2 + e];
                    if (fabsf(t - 1.0f) < 1.5e-3f)
                        t = recompute_t(&AH[rloc * AP], &AL[rloc * AP],
                                        Wt_self + j * 128, Wt_neigh + j * 128);
                    op[gr * OC + j] = (t >= 1.0f) ? sigmoidf_(x) : 0.0f;
                }
            }
        }
    }
}

extern "C" void kernel_launch(void* const* d_in, const int* in_sizes, int n_in,
                              void* d_out, int out_size)
{
    const float* h0   = (const float*)d_in[0];
    const float* h1   = (const float*)d_in[1];
    const float* h2   = (const float*)d_in[2];
    const float* Wl1  = (const float*)d_in[3];
    const float* Wr1  = (const float*)d_in[4];
    const float* Wlt1 = (const float*)d_in[5];
    const float* Wrt1 = (const float*)d_in[6];
    const float* Wl2  = (const float*)d_in[7];
    const float* Wr2  = (const float*)d_in[8];
    const float* Wlt2 = (const float*)d_in[9];
    const float* Wrt2 = (const float*)d_in[10];

    int N = in_sizes[0] / 128;

    int smem1 = 2 * 32 * AP * 4 + 2 * (256 * BPC * 4 + 128 * BPC * 4) + 64;  // 70,720 B
    int smem2 = 2 * 32 * AP * 4 + 2 * (128 * BPC * 4) + 64;                  // 46,144 B
    cudaFuncSetAttribute(signn_gemm<true>,  cudaFuncAttributeMaxDynamicSharedMemorySize, smem1);
    cudaFuncSetAttribute(signn_gemm<false>, cudaFuncAttributeMaxDynamicSharedMemorySize, smem2);

    long rows = 6L * N;
    int grid1 = (int)((rows + 31) / 32);
    int grid2 = (N + 31) / 32;

    presplit<<<384, 128>>>(Wl1, Wr1, Wlt1, Wrt1, Wl2, Wr2, Wlt2, Wrt2);
    signn_gemm<true><<<grid1, 256, smem1>>>(h0, h1, h2, Wlt1, Wrt1, nullptr, N);
    signn_gemm<false><<<grid2, 256, smem2>>>(nullptr, nullptr, nullptr, Wlt2, Wrt2,
                                             (float*)d_out, N);
}

// round 14
// speedup vs baseline: 1.3668x; 1.0093x over previous
#include <cuda_runtime.h>
#include <cuda_fp16.h>
#include <math.h>
#include <stdint.h>

// ---------------- global scratch ----------------
__device__ float    g_outs[76800000];     // layer-1 out_s: 600000 x 128 (fp32)
// B weights, pre-split fp16 hi/lo, DE-INTERLEAVED (x cols then t cols),
// chunk16-major padded: [chunk(16)][col][12 u32] (8 u32 = 16 k packed half2 + 4 pad)
__device__ uint32_t g_B1h[16 * 256 * 12], g_B1l[16 * 256 * 12];
__device__ uint32_t g_B2h[16 * 128 * 12], g_B2l[16 * 128 * 12];

// ---------------- helpers ----------------
static __device__ __forceinline__ void split2h(float x, float y, uint32_t& ph, uint32_t& pl) {
    __half hx = __float2half(x);
    __half hy = __float2half(y);
    float rx = x - __half2float(hx);
    float ry = y - __half2float(hy);
    __half2 H = __halves2half2(hx, hy);
    __half2 L = __halves2half2(__float2half(rx), __float2half(ry));
    ph = *reinterpret_cast<uint32_t*>(&H);
    pl = *reinterpret_cast<uint32_t*>(&L);
}

static __device__ __forceinline__ void mma16(float c[4], const uint32_t a[4],
                                             uint32_t b0, uint32_t b1) {
    asm volatile(
        "mma.sync.aligned.m16n8k16.row.col.f32.f16.f16.f32 "
        "{%0,%1,%2,%3}, {%4,%5,%6,%7}, {%8,%9}, {%0,%1,%2,%3};"
        : "+f"(c[0]), "+f"(c[1]), "+f"(c[2]), "+f"(c[3])
        : "r"(a[0]), "r"(a[1]), "r"(a[2]), "r"(a[3]), "r"(b0), "r"(b1));
}

static __device__ __forceinline__ void ldsm4(uint32_t& r0, uint32_t& r1,
                                             uint32_t& r2, uint32_t& r3, uint32_t saddr) {
    asm volatile("ldmatrix.sync.aligned.m8n8.x4.shared.b16 {%0,%1,%2,%3}, [%4];"
                 : "=r"(r0), "=r"(r1), "=r"(r2), "=r"(r3) : "r"(saddr));
}

static __device__ __forceinline__ void bulk_g2s(uint32_t dst, const void* src,
                                                uint32_t bytes, uint32_t mbar) {
    asm volatile(
        "cp.async.bulk.shared::cta.global.mbarrier::complete_tx::bytes [%0], [%1], %2, [%3];"
        :: "r"(dst), "l"(src), "r"(bytes), "r"(mbar) : "memory");
}

static __device__ __forceinline__ void mbar_expect(uint32_t mbar, uint32_t bytes) {
    asm volatile("mbarrier.arrive.expect_tx.shared.b64 _, [%0], %1;"
                 :: "r"(mbar), "r"(bytes) : "memory");
}

static __device__ __forceinline__ void mbar_arrive(uint32_t mbar) {
    asm volatile("mbarrier.arrive.release.cta.shared::cta.b64 _, [%0];"
                 :: "r"(mbar) : "memory");
}

static __device__ __forceinline__ void mbar_wait(uint32_t mbar, uint32_t parity) {
    asm volatile(
        "{\n\t.reg .pred P1;\n\t"
        "WL_%=:\n\t"
        "mbarrier.try_wait.parity.acquire.cta.shared::cta.b64 P1, [%0], %1, 0x989680;\n\t"
        "@P1 bra.uni WD_%=;\n\t"
        "bra.uni WL_%=;\n\t"
        "WD_%=:\n\t}"
        :: "r"(mbar), "r"(parity) : "memory");
}

static __device__ __forceinline__ float sigmoidf_(float v) {
    return 1.0f / (1.0f + expf(-v));
}

// accurate recompute of t near threshold (A stored fp16 hi+lo, residual ~2^-24)
static __device__ __noinline__ float recompute_t(const uint32_t* AHrow, const uint32_t* ALrow,
                                                 const float* __restrict__ wt,
                                                 const float* __restrict__ wr) {
    float s = 0.0f;
    for (int k2 = 0; k2 < 64; k2++) {
        __half2 uh = *reinterpret_cast<const __half2*>(&AHrow[k2]);
        __half2 ul = *reinterpret_cast<const __half2*>(&ALrow[k2]);
        float a0 = __half2float(__low2half(uh)) + __half2float(__low2half(ul));
        float a1 = __half2float(__high2half(uh)) + __half2float(__high2half(ul));
        s += a0 * wt[2 * k2] + a1 * wt[2 * k2 + 1];
    }
    for (int k2 = 64; k2 < 128; k2++) {
        __half2 uh = *reinterpret_cast<const __half2*>(&AHrow[k2]);
        __half2 ul = *reinterpret_cast<const __half2*>(&ALrow[k2]);
        float a0 = __half2float(__low2half(uh)) + __half2float(__low2half(ul));
        float a1 = __half2float(__high2half(uh)) + __half2float(__high2half(ul));
        s += a0 * wr[2 * k2 - 128] + a1 * wr[2 * k2 - 127];
    }
    return s;
}

// ---------------- weight pre-split (de-interleaved, chunk16-major, 48B stride) ----------------
__global__ void presplit(const float* __restrict__ Wl1, const float* __restrict__ Wr1,
                         const float* __restrict__ Wlt1, const float* __restrict__ Wrt1,
                         const float* __restrict__ Wl2, const float* __restrict__ Wr2,
                         const float* __restrict__ Wlt2, const float* __restrict__ Wrt2) {
    int c = blockIdx.x;          // 0..383
    int t = threadIdx.x;         // 0..127 -> k pair (2t, 2t+1)
    bool is1 = c < 256;
    int cc = is1 ? c : c - 256;
    int ncol = is1 ? 256 : 128;
    int hc = ncol >> 1;
    bool isT = cc >= hc;
    int j = isT ? cc - hc : cc;
    int k = 2 * t;
    const float* base;
    if (is1) base = (k < 128) ? (isT ? Wlt1 : Wl1) : (isT ? Wrt1 : Wr1);
    else     base = (k < 128) ? (isT ? Wlt2 : Wl2) : (isT ? Wrt2 : Wr2);
    int kk = k & 127;
    float x = base[j * 128 + kk], y = base[j * 128 + kk + 1];
    uint32_t ph, pl;
    split2h(x, y, ph, pl);
    int chunk = t >> 3, p = t & 7;      // 16k chunks, 8 u32 data per col
    long idx = ((long)chunk * ncol + cc) * 12 + p;
    if (is1) { g_B1h[idx] = ph; g_B1l[idx] = pl; }
    else     { g_B2h[idx] = ph; g_B2l[idx] = pl; }
}

// ---------------- fused GEMM + epilogue (BM=32, 256 thr, warp-decoupled ring) ----------------
#define AP 132   // uint32 per A row (128 data + 4 pad) -> 528B row stride
#define BPC 12   // uint32 per B col per 16-k chunk -> 48B col stride (16B-aligned)

template <bool L1, int MAXB>
__global__ void __launch_bounds__(256, MAXB)
signn_gemm(const float* __restrict__ h0, const float* __restrict__ h1,
           const float* __restrict__ h2,
           const float* __restrict__ Wt_self, const float* __restrict__ Wt_neigh,
           float* __restrict__ outp, int N)
{
    constexpr int NCOL = L1 ? 256 : 128;
    constexpr int HC   = NCOL / 2;        // x/t half size in cols
    constexpr int NXTW = HC / 4 / 8;      // x-tiles per warp (l1:4, l2:2)
    constexpr int NXP  = NXTW / 2;        // ldsm 16-col pairs (l1:2, l2:1)
    constexpr int OC   = L1 ? 128 : 64;   // output features
    constexpr uint32_t SRC_CHUNK = NCOL * BPC;            // u32 per chunk in gmem
    constexpr uint32_t BH_B = NCOL * BPC * 4;             // hi bytes per chunk
    constexpr uint32_t BL_B = L1 ? (HC * BPC * 4) : 0;    // lo bytes (x-half only)
    constexpr uint32_t BUF_B = BH_B + BL_B;

    extern __shared__ uint32_t sm[];
    uint32_t* AH = sm;                        // 32 x AP
    uint32_t* AL = sm + 32 * AP;
    uint32_t* Bb = sm + 2 * 32 * AP;          // 2 buffers x (bh | bl)
    uint32_t* mbars = Bb + 2 * (BUF_B / 4);   // full0, full1, empty0, empty1

    const int tid = threadIdx.x;
    const int w = tid >> 5, l = tid & 31;     // 8 warps
    const int g = l >> 2, tg = l & 3;
    const int warpM = w >> 2, warpN = w & 3;  // 2 m x 4 n
    const long rows = L1 ? 6L * N : (long)N;
    const long blockRow = (long)blockIdx.x * 32;
    const uint32_t* Bh = L1 ? g_B1h : g_B2h;
    const uint32_t* Bl = L1 ? g_B1l : g_B2l;
    float* op = L1 ? g_outs : outp;

    const uint32_t mb0 = (uint32_t)__cvta_generic_to_shared(mbars);
    const uint32_t mb1 = mb0 + 8;
    const uint32_t me0 = mb0 + 16;
    const uint32_t me1 = mb0 + 24;
    const uint32_t bBase = (uint32_t)__cvta_generic_to_shared(Bb);

    // ldmatrix lane geometry
    const int rowA = l & 15;
    const int kofA = (l >= 16) ? 8 : 0;
    const int nofB = (l & 7) + ((l >= 16) ? 8 : 0);
    const int kofB = (l & 8) ? 8 : 0;

    if (tid == 0) {
        asm volatile("mbarrier.init.shared.b64 [%0], 1;" :: "r"(mb0) : "memory");
        asm volatile("mbarrier.init.shared.b64 [%0], 1;" :: "r"(mb1) : "memory");
        asm volatile("mbarrier.init.shared.b64 [%0], 8;" :: "r"(me0) : "memory");
        asm volatile("mbarrier.init.shared.b64 [%0], 8;" :: "r"(me1) : "memory");
    }
    __syncthreads();

    // ---- kick off bulk prefetch of chunks 0 and 1 ----
    if (tid == 0) {
        mbar_expect(mb0, BUF_B);
        bulk_g2s(bBase, Bh + 0 * SRC_CHUNK, BH_B, mb0);
        if (L1) bulk_g2s(bBase + BH_B, Bl + 0 * SRC_CHUNK, BL_B, mb0);
        mbar_expect(mb1, BUF_B);
        bulk_g2s(bBase + BUF_B, Bh + 1 * SRC_CHUNK, BH_B, mb1);
        if (L1) bulk_g2s(bBase + BUF_B + BH_B, Bl + 1 * SRC_CHUNK, BL_B, mb1);
    }

    // ---- stage A: 32 rows (4 per warp), gather + split to fp16 hi/lo ----
#pragma unroll
    for (int rr = 0; rr < 4; rr++) {
        int row = w * 4 + rr;
        long gr = blockRow + row;
        long grc = gr < rows ? gr : rows - 1;
        float4 xv, nv;
        if (L1) {
            if (grc < N) {
                xv = ((const float4*)h0)[grc * 32 + l];
                const float4* p = (const float4*)h1 + grc * 5 * 32 + l;
                float4 a0 = p[0], a1 = p[32], a2 = p[64], a3 = p[96], a4 = p[128];
                nv.x = (a0.x + a1.x + a2.x + a3.x + a4.x) * 0.2f;
                nv.y = (a0.y + a1.y + a2.y + a3.y + a4.y) * 0.2f;
                nv.z = (a0.z + a1.z + a2.z + a3.z + a4.z) * 0.2f;
                nv.w = (a0.w + a1.w + a2.w + a3.w + a4.w) * 0.2f;
            } else {
                long q = grc - N;
                xv = ((const float4*)h1)[q * 32 + l];
                const float4* p = (const float4*)h2 + q * 2 * 32 + l;
                float4 a0 = p[0], a1 = p[32];
                nv.x = (a0.x + a1.x) * 0.5f;
                nv.y = (a0.y + a1.y) * 0.5f;
                nv.z = (a0.z + a1.z) * 0.5f;
                nv.w = (a0.w + a1.w) * 0.5f;
            }
        } else {
            xv = ((const float4*)g_outs)[grc * 32 + l];
            const float4* p = (const float4*)g_outs + ((long)N + grc * 5) * 32 + l;
            float4 a0 = p[0], a1 = p[32], a2 = p[64], a3 = p[96], a4 = p[128];
            nv.x = (a0.x + a1.x + a2.x + a3.x + a4.x) * 0.2f;
            nv.y = (a0.y + a1.y + a2.y + a3.y + a4.y) * 0.2f;
            nv.z = (a0.z + a1.z + a2.z + a3.z + a4.z) * 0.2f;
            nv.w = (a0.w + a1.w + a2.w + a3.w + a4.w) * 0.2f;
        }
        uint32_t h0p, l0p, h1p, l1p;
        split2h(xv.x, xv.y, h0p, l0p);
        split2h(xv.z, xv.w, h1p, l1p);
        *(uint2*)&AH[row * AP + 2 * l] = make_uint2(h0p, h1p);
        *(uint2*)&AL[row * AP + 2 * l] = make_uint2(l0p, l1p);
        split2h(nv.x, nv.y, h0p, l0p);
        split2h(nv.z, nv.w, h1p, l1p);
        *(uint2*)&AH[row * AP + 64 + 2 * l] = make_uint2(h0p, h1p);
        *(uint2*)&AL[row * AP + 64 + 2 * l] = make_uint2(l0p, l1p);
    }
    __syncthreads();   // A visible to all warps

    float accx[NXTW][4], acct[NXTW][4];
#pragma unroll
    for (int nt = 0; nt < NXTW; nt++)
#pragma unroll
        for (int e = 0; e < 4; e++) { accx[nt][e] = 0.0f; acct[nt][e] = 0.0f; }

    const uint32_t aHbase = (uint32_t)__cvta_generic_to_shared(AH);
    const uint32_t aLbase = (uint32_t)__cvta_generic_to_shared(AL);

    // ---- main loop: 16 chunks of BK=16, warp-decoupled double-buffer ring ----
#pragma unroll 1
    for (int kc = 0; kc < 16; kc++) {
        const int b = kc & 1;
        const uint32_t mbb = b ? mb1 : mb0;
        const uint32_t meb = b ? me1 : me0;
        mbar_wait(mbb, (kc >> 1) & 1);     // chunk kc data ready

        const uint32_t bHc = bBase + b * BUF_B;          // hi: all NCOL cols
        const uint32_t bLc = bHc + BH_B;                 // lo: x-half cols only
        const int kb = kc * 16;

        uint32_t ah[4], al[4];
        {
            uint32_t ro = (uint32_t)(warpM * 16 + rowA) * (AP * 4) + (kb + kofA) * 2;
            ldsm4(ah[0], ah[1], ah[2], ah[3], aHbase + ro);
            ldsm4(al[0], al[1], al[2], al[3], aLbase + ro);
        }
#pragma unroll
        for (int ntp = 0; ntp < NXP; ntp++) {
            int xcol = warpN * (NXTW * 8) + ntp * 16 + nofB;
            uint32_t koff = (uint32_t)kofB * 2;
            // ---- x-gate ----
            uint32_t bh[4], bl[4];
            ldsm4(bh[0], bh[1], bh[2], bh[3], bHc + (uint32_t)xcol * 48 + koff);
            if (L1)
                ldsm4(bl[0], bl[1], bl[2], bl[3], bLc + (uint32_t)xcol * 48 + koff);
#pragma unroll
            for (int tile = 0; tile < 2; tile++) {
                int nt = ntp * 2 + tile;
                mma16(accx[nt], ah, bh[2 * tile], bh[2 * tile + 1]);
                if (L1)
                    mma16(accx[nt], ah, bl[2 * tile], bl[2 * tile + 1]);
                mma16(accx[nt], al, bh[2 * tile], bh[2 * tile + 1]);
            }
            // ---- t-gate: 1 term ----
            uint32_t bt[4];
            ldsm4(bt[0], bt[1], bt[2], bt[3],
                  bHc + (uint32_t)(HC + xcol) * 48 + koff);
#pragma unroll
            for (int tile = 0; tile < 2; tile++)
                mma16(acct[ntp * 2 + tile], ah, bt[2 * tile], bt[2 * tile + 1]);
        }

        // warp done reading buffer b for chunk kc -> lane 0 signals empty
        if (kc + 2 < 16) {
            if (l == 0) mbar_arrive(meb);
            if (tid == 0) {
                mbar_wait(meb, (kc >> 1) & 1);   // all 8 warps done with buffer b
                mbar_expect(mbb, BUF_B);
                bulk_g2s(bBase + b * BUF_B, Bh + (kc + 2) * SRC_CHUNK, BH_B, mbb);
                if (L1) bulk_g2s(bBase + b * BUF_B + BH_B,
                                 Bl + (kc + 2) * SRC_CHUNK, BL_B, mbb);
            }
        }
    }

    // ---- epilogue: out = sigmoid(x) * spike(t), guarded near threshold ----
#pragma unroll
    for (int nt = 0; nt < NXTW; nt++) {
        int j0 = warpN * (NXTW * 8) + nt * 8 + tg * 2;
#pragma unroll
        for (int half = 0; half < 2; half++) {
            int rloc = warpM * 16 + g + half * 8;
            long gr = blockRow + rloc;
            if (gr < rows) {
#pragma unroll
                for (int e = 0; e < 2; e++) {
                    int j = j0 + e;
                    float x = accx[nt][half * 2 + e];
                    float t = acct[nt][half * 2 + e];
                    if (fabsf(t - 1.0f) < 1.5e-3f)
                        t = recompute_t(&AH[rloc * AP], &AL[rloc * AP],
                                        Wt_self + j * 128, Wt_neigh + j * 128);
                    op[gr * OC + j] = (t >= 1.0f) ? sigmoidf_(x) : 0.0f;
                }
            }
        }
    }
}

extern "C" void kernel_launch(void* const* d_in, const int* in_sizes, int n_in,
                              void* d_out, int out_size)
{
    const float* h0   = (const float*)d_in[0];
    const float* h1   = (const float*)d_in[1];
    const float* h2   = (const float*)d_in[2];
    const float* Wl1  = (const float*)d_in[3];
    const float* Wr1  = (const float*)d_in[4];
    const float* Wlt1 = (const float*)d_in[5];
    const float* Wrt1 = (const float*)d_in[6];
    const float* Wl2  = (const float*)d_in[7];
    const float* Wr2  = (const float*)d_in[8];
    const float* Wlt2 = (const float*)d_in[9];
    const float* Wrt2 = (const float*)d_in[10];

    int N = in_sizes[0] / 128;

    int smem1 = 2 * 32 * AP * 4 + 2 * (256 * BPC * 4 + 128 * BPC * 4) + 64;  // 70,720 B
    int smem2 = 2 * 32 * AP * 4 + 2 * (128 * BPC * 4) + 64;                  // 46,144 B
    cudaFuncSetAttribute((const void*)signn_gemm<true, 3>,
                         cudaFuncAttributeMaxDynamicSharedMemorySize, smem1);
    cudaFuncSetAttribute((const void*)signn_gemm<false, 4>,
                         cudaFuncAttributeMaxDynamicSharedMemorySize, smem2);

    long rows = 6L * N;
    int grid1 = (int)((rows + 31) / 32);
    int grid2 = (N + 31) / 32;

    presplit<<<384, 128>>>(Wl1, Wr1, Wlt1, Wrt1, Wl2, Wr2, Wlt2, Wrt2);
    signn_gemm<true, 3><<<grid1, 256, smem1>>>(h0, h1, h2, Wlt1, Wrt1, nullptr, N);
    signn_gemm<false, 4><<<grid2, 256, smem2>>>(nullptr, nullptr, nullptr, Wlt2, Wrt2,
                                                (float*)d_out, N);
}